// round 1
// baseline (speedup 1.0000x reference)
#include <cuda_runtime.h>
#include <math.h>

// Problem constants (fixed shapes from reference setup_inputs)
#define BQ      4
#define LSEQ    2048
#define DMODEL  512
#define NHEAD   8
#define HDIM    64
#define FFND    2048
#define BL      (BQ * LSEQ)        // 8192 rows
#define QKV3    (3 * DMODEL)       // 1536
#define SCHUNK  512
#define NCHUNK  4

// Scratch (static device globals: allocation-free per harness rules)
__device__ float g_qkv [BL * QKV3];     // 50.3 MB
__device__ float g_attn[BL * DMODEL];   // 16.8 MB (reused for pre-LN2)
__device__ float g_x1  [BL * DMODEL];   // 16.8 MB
__device__ float g_ffn [BL * FFND];     // 67.1 MB

// ---------------------------------------------------------------------------
// SGEMM: C[M,N] = A[M,K] @ B[K,N] (+bias[N]) (GELU?) (+res[M,N]?)
// 128x128 block tile, BK=8, 256 threads, 8x8 per-thread microtile.
// M,N multiples of 128; K multiple of 8 (all true for our shapes).
// ---------------------------------------------------------------------------
template<int GELU, int HASRES>
__global__ __launch_bounds__(256) void sgemm_kernel(
    const float* __restrict__ A, const float* __restrict__ B,
    const float* __restrict__ bias, const float* __restrict__ res,
    float* __restrict__ C, int M, int N, int K)
{
    __shared__ float As[8][128];
    __shared__ float Bs[8][128];

    const int tid   = threadIdx.x;
    const int mBase = blockIdx.y * 128;
    const int nBase = blockIdx.x * 128;

    const int aRow = tid >> 1;            // 0..127
    const int aKc  = (tid & 1) * 4;       // 0 or 4
    const int bRow = tid >> 5;            // 0..7
    const int bCol = (tid & 31) * 4;      // 0..124

    const float* Aptr = A + (size_t)(mBase + aRow) * K + aKc;
    const float* Bptr = B + (size_t)bRow * N + nBase + bCol;

    const int ty = tid >> 4, tx = tid & 15;
    const int m0 = ty * 8,   n0 = tx * 8;

    float acc[8][8];
#pragma unroll
    for (int i = 0; i < 8; i++)
#pragma unroll
        for (int j = 0; j < 8; j++) acc[i][j] = 0.f;

    for (int k0 = 0; k0 < K; k0 += 8) {
        float4 av = *(const float4*)(Aptr + k0);
        float4 bv = *(const float4*)(Bptr + (size_t)k0 * N);
        As[aKc + 0][aRow] = av.x;
        As[aKc + 1][aRow] = av.y;
        As[aKc + 2][aRow] = av.z;
        As[aKc + 3][aRow] = av.w;
        *(float4*)&Bs[bRow][bCol] = bv;
        __syncthreads();

#pragma unroll
        for (int kk = 0; kk < 8; kk++) {
            float4 a0 = *(const float4*)&As[kk][m0];
            float4 a1 = *(const float4*)&As[kk][m0 + 4];
            float4 b0 = *(const float4*)&Bs[kk][n0];
            float4 b1 = *(const float4*)&Bs[kk][n0 + 4];
            float ar[8] = {a0.x, a0.y, a0.z, a0.w, a1.x, a1.y, a1.z, a1.w};
            float br[8] = {b0.x, b0.y, b0.z, b0.w, b1.x, b1.y, b1.z, b1.w};
#pragma unroll
            for (int i = 0; i < 8; i++)
#pragma unroll
                for (int j = 0; j < 8; j++)
                    acc[i][j] += ar[i] * br[j];
        }
        __syncthreads();
    }

#pragma unroll
    for (int i = 0; i < 8; i++) {
        const int row = mBase + m0 + i;
        const size_t base = (size_t)row * N + nBase + n0;
#pragma unroll
        for (int j = 0; j < 8; j++) {
            const int col = nBase + n0 + j;
            float v = acc[i][j] + bias[col];
            if (GELU) v = 0.5f * v * (1.0f + erff(v * 0.70710678118654752f));
            if (HASRES) v += res[base + j];
            C[base + j] = v;
        }
    }
}

// ---------------------------------------------------------------------------
// Chunked local attention (flash-style, fp32).
// grid: 512 blocks = 32 (b*h) x 4 chunks x 4 q-subtiles; 128 threads.
// Each thread owns ONE query row: q[64] + acc[64] in registers, thread-local
// online softmax (no cross-thread reductions). Keys iterate the clamped
// 3-chunk window in 16-row smem tiles (broadcast LDS reads).
// ---------------------------------------------------------------------------
#define ATT_TK 16

__global__ __launch_bounds__(128) void attn_kernel(
    const float* __restrict__ qkv, const int* __restrict__ mask,
    float* __restrict__ out)
{
    const int blk = blockIdx.x;
    const int qt  = blk & 3;
    const int c   = (blk >> 2) & 3;
    const int bh  = blk >> 4;               // 0..31
    const int b   = bh >> 3;
    const int h   = bh & 7;
    const int tid = threadIdx.x;
    const int lq  = c * SCHUNK + qt * 128 + tid;

    // Load q row, pre-scaled by 1/sqrt(HD) = 0.125
    const float* qrow = qkv + ((size_t)(b * LSEQ + lq)) * QKV3 + h * HDIM;
    float q[HDIM];
#pragma unroll
    for (int d4 = 0; d4 < 16; d4++) {
        float4 v = *(const float4*)(qrow + d4 * 4);
        q[d4 * 4 + 0] = v.x * 0.125f;
        q[d4 * 4 + 1] = v.y * 0.125f;
        q[d4 * 4 + 2] = v.z * 0.125f;
        q[d4 * 4 + 3] = v.w * 0.125f;
    }

    float acc[HDIM];
#pragma unroll
    for (int d = 0; d < HDIM; d++) acc[d] = 0.f;
    float mrun = -1e30f, lrun = 0.f;

    __shared__ float ks[ATT_TK][HDIM];
    __shared__ float vs[ATT_TK][HDIM];
    __shared__ int   msk[ATT_TK];

    int k0 = (c - 1) * SCHUNK; if (k0 < 0) k0 = 0;
    int k1 = (c + 2) * SCHUNK; if (k1 > LSEQ) k1 = LSEQ;

    for (int kt = k0; kt < k1; kt += ATT_TK) {
        __syncthreads();
        // Stage K and V tiles: 16 rows x 64 floats each; 2 float4 per thread/buffer.
#pragma unroll
        for (int r = 0; r < 2; r++) {
            const int fi = tid + r * 128;       // 0..255
            const int j  = fi >> 4;
            const int d4 = fi & 15;
            const float* kp = qkv + ((size_t)(b * LSEQ + kt + j)) * QKV3
                              + DMODEL + h * HDIM + d4 * 4;
            *(float4*)&ks[j][d4 * 4] = *(const float4*)kp;
            *(float4*)&vs[j][d4 * 4] = *(const float4*)(kp + DMODEL);
        }
        if (tid < ATT_TK) msk[tid] = mask[b * LSEQ + kt + tid];
        __syncthreads();

        // Scores for this tile
        float s[ATT_TK];
        float tmax = -1e30f;
#pragma unroll
        for (int j = 0; j < ATT_TK; j++) {
            float dot = 0.f;
#pragma unroll
            for (int d4 = 0; d4 < 16; d4++) {
                float4 kv = *(const float4*)&ks[j][d4 * 4];
                dot += q[d4 * 4 + 0] * kv.x;
                dot += q[d4 * 4 + 1] * kv.y;
                dot += q[d4 * 4 + 2] * kv.z;
                dot += q[d4 * 4 + 3] * kv.w;
            }
            s[j] = msk[j] ? -1e30f : dot;
            tmax = fmaxf(tmax, s[j]);
        }

        // Online softmax update (thread-local)
        const float mnew  = fmaxf(mrun, tmax);
        const float scale = __expf(mrun - mnew);
        lrun *= scale;
#pragma unroll
        for (int d = 0; d < HDIM; d++) acc[d] *= scale;
        mrun = mnew;

#pragma unroll
        for (int j = 0; j < ATT_TK; j++) {
            const float p = __expf(s[j] - mnew);
            lrun += p;
#pragma unroll
            for (int d4 = 0; d4 < 16; d4++) {
                float4 vv = *(const float4*)&vs[j][d4 * 4];
                acc[d4 * 4 + 0] += p * vv.x;
                acc[d4 * 4 + 1] += p * vv.y;
                acc[d4 * 4 + 2] += p * vv.z;
                acc[d4 * 4 + 3] += p * vv.w;
            }
        }
    }

    // Write normalized output into merged [B,L,D] layout
    const float invl = 1.0f / lrun;
    float* op = out + ((size_t)(b * LSEQ + lq)) * DMODEL + h * HDIM;
#pragma unroll
    for (int d4 = 0; d4 < 16; d4++) {
        float4 o;
        o.x = acc[d4 * 4 + 0] * invl;
        o.y = acc[d4 * 4 + 1] * invl;
        o.z = acc[d4 * 4 + 2] * invl;
        o.w = acc[d4 * 4 + 3] * invl;
        *(float4*)(op + d4 * 4) = o;
    }
}

// ---------------------------------------------------------------------------
// LayerNorm over last dim (512). One block per row, 128 threads x float4.
// Safe in-place: all reads happen before the barrier-protected writes.
// ---------------------------------------------------------------------------
__global__ __launch_bounds__(128) void ln_kernel(
    const float* __restrict__ in, const float* __restrict__ gg,
    const float* __restrict__ bb, float* __restrict__ out)
{
    const int row = blockIdx.x, tid = threadIdx.x;
    const float* p = in + (size_t)row * DMODEL;
    float4 v = *(const float4*)(p + tid * 4);
    float s  = v.x + v.y + v.z + v.w;
    float ss = v.x * v.x + v.y * v.y + v.z * v.z + v.w * v.w;
#pragma unroll
    for (int o = 16; o > 0; o >>= 1) {
        s  += __shfl_xor_sync(0xffffffffu, s,  o);
        ss += __shfl_xor_sync(0xffffffffu, ss, o);
    }
    __shared__ float sh[8];
    const int w = tid >> 5, ln = tid & 31;
    if (ln == 0) { sh[w] = s; sh[4 + w] = ss; }
    __syncthreads();
    s  = sh[0] + sh[1] + sh[2] + sh[3];
    ss = sh[4] + sh[5] + sh[6] + sh[7];
    const float mu  = s * (1.0f / DMODEL);
    const float var = ss * (1.0f / DMODEL) - mu * mu;
    const float inv = rsqrtf(var + 1e-5f);
    float4 gv = *(const float4*)(gg + tid * 4);
    float4 bv = *(const float4*)(bb + tid * 4);
    float4 o4;
    o4.x = (v.x - mu) * inv * gv.x + bv.x;
    o4.y = (v.y - mu) * inv * gv.y + bv.y;
    o4.z = (v.z - mu) * inv * gv.z + bv.z;
    o4.w = (v.w - mu) * inv * gv.w + bv.w;
    *(float4*)(out + (size_t)row * DMODEL + tid * 4) = o4;
}

// ---------------------------------------------------------------------------
extern "C" void kernel_launch(void* const* d_in, const int* in_sizes, int n_in,
                              void* d_out, int out_size)
{
    const float* x      = (const float*)d_in[0];
    const int*   mask   = (const int*)  d_in[1];
    const float* qkv_w  = (const float*)d_in[2];
    const float* qkv_b  = (const float*)d_in[3];
    const float* out_w  = (const float*)d_in[4];
    const float* out_b  = (const float*)d_in[5];
    const float* ffn_w1 = (const float*)d_in[6];
    const float* ffn_b1 = (const float*)d_in[7];
    const float* ffn_w2 = (const float*)d_in[8];
    const float* ffn_b2 = (const float*)d_in[9];
    const float* ln1_g  = (const float*)d_in[10];
    const float* ln1_b  = (const float*)d_in[11];
    const float* ln2_g  = (const float*)d_in[12];
    const float* ln2_b  = (const float*)d_in[13];
    float* out = (float*)d_out;

    float *qkvp, *attnp, *x1p, *ffnp;
    cudaGetSymbolAddress((void**)&qkvp,  g_qkv);
    cudaGetSymbolAddress((void**)&attnp, g_attn);
    cudaGetSymbolAddress((void**)&x1p,   g_x1);
    cudaGetSymbolAddress((void**)&ffnp,  g_ffn);

    // 1) QKV = X @ qkv_w + qkv_b                      [8192,1536]
    sgemm_kernel<0,0><<<dim3(QKV3 / 128, BL / 128), 256>>>(
        x, qkv_w, qkv_b, nullptr, qkvp, BL, QKV3, DMODEL);

    // 2) Chunked local attention -> merged [B,L,D]
    attn_kernel<<<512, 128>>>(qkvp, mask, attnp);

    // 3) pre1 = x + (attn @ out_w + out_b)            [8192,512]
    sgemm_kernel<0,1><<<dim3(DMODEL / 128, BL / 128), 256>>>(
        attnp, out_w, out_b, x, x1p, BL, DMODEL, DMODEL);

    // 4) x1 = LN1(pre1)  (in-place)
    ln_kernel<<<BL, 128>>>(x1p, ln1_g, ln1_b, x1p);

    // 5) h = gelu(x1 @ ffn_w1 + ffn_b1)               [8192,2048]
    sgemm_kernel<1,0><<<dim3(FFND / 128, BL / 128), 256>>>(
        x1p, ffn_w1, ffn_b1, nullptr, ffnp, BL, FFND, DMODEL);

    // 6) pre2 = x1 + (h @ ffn_w2 + ffn_b2)            [8192,512] (reuse g_attn)
    sgemm_kernel<0,1><<<dim3(DMODEL / 128, BL / 128), 256>>>(
        ffnp, ffn_w2, ffn_b2, x1p, attnp, BL, DMODEL, FFND);

    // 7) out = LN2(pre2)
    ln_kernel<<<BL, 128>>>(attnp, ln2_g, ln2_b, out);
}

// round 2
// speedup vs baseline: 1.4472x; 1.4472x over previous
#include <cuda_runtime.h>
#include <math.h>
#include <stdint.h>

// Problem constants (fixed shapes from reference setup_inputs)
#define BQ      4
#define LSEQ    2048
#define DMODEL  512
#define NHEAD   8
#define HDIM    64
#define FFND    2048
#define BL      (BQ * LSEQ)        // 8192 rows
#define QKV3    (3 * DMODEL)       // 1536
#define SCHUNK  512
#define NCHUNK  4

// Scratch (static device globals: allocation-free per harness rules)
__device__ float g_qkv [BL * QKV3];     // 50.3 MB
__device__ float g_attn[BL * DMODEL];   // 16.8 MB (reused for pre-LN2)
__device__ float g_x1  [BL * DMODEL];   // 16.8 MB
__device__ float g_ffn [BL * FFND];     // 67.1 MB

// ---------------------------------------------------------------------------
// TF32 round-to-nearest conversion (value kept in f32 register, low mantissa
// bits now zero — the HMMA unit reads it as tf32).
// ---------------------------------------------------------------------------
__device__ __forceinline__ float cvt_tf32(float x) {
    uint32_t u;
    asm("cvt.rna.tf32.f32 %0, %1;" : "=r"(u) : "f"(x));
    return __uint_as_float(u);
}

__device__ __forceinline__ void mma_tf32(float* d, const uint32_t* a, const uint32_t* b) {
    asm volatile(
        "mma.sync.aligned.m16n8k8.row.col.f32.tf32.tf32.f32 "
        "{%0,%1,%2,%3}, {%4,%5,%6,%7}, {%8,%9}, {%0,%1,%2,%3};"
        : "+f"(d[0]), "+f"(d[1]), "+f"(d[2]), "+f"(d[3])
        : "r"(a[0]), "r"(a[1]), "r"(a[2]), "r"(a[3]), "r"(b[0]), "r"(b[1]));
}

// ---------------------------------------------------------------------------
// TF32 tensor-core GEMM: C[M,N] = A[M,K] @ B[K,N] (+bias) (GELU?) (+res?)
// Block 128x128xBK16, 256 threads = 8 warps in 2(M)x4(N) layout,
// warp tile 64x32 = 4x4 m16n8k8 fragments. Smem stride 136 -> conflict-free
// fragment loads (bank = 8*k + idx). Register prefetch of next k-tile.
// Requires: M,N % 128 == 0, K % 16 == 0.
// ---------------------------------------------------------------------------
#define LDS_ 136

template<int GELU, int HASRES>
__global__ __launch_bounds__(256) void tgemm_kernel(
    const float* __restrict__ A, const float* __restrict__ B,
    const float* __restrict__ bias, const float* __restrict__ res,
    float* __restrict__ C, int M, int N, int K)
{
    __shared__ float As[16 * LDS_];
    __shared__ float Bs[16 * LDS_];

    const int tid   = threadIdx.x;
    const int mBase = blockIdx.y * 128;
    const int nBase = blockIdx.x * 128;

    const int lane = tid & 31;
    const int wid  = tid >> 5;           // 0..7
    const int grp  = lane >> 2;          // 0..7
    const int qd   = lane & 3;           // 0..3
    const int mWarp = (wid & 1) * 64;
    const int nWarp = (wid >> 1) * 32;

    // Global-load mapping
    const int aRow = tid >> 2;           // 0..63 (+64 on second pass)
    const int aKc  = (tid & 3) * 4;      // 0,4,8,12
    const int bK   = tid >> 5;           // 0..7 (+8 on second pass)
    const int bCol = (tid & 31) * 4;     // 0..124

    const float* Ap = A + (size_t)(mBase + aRow) * K + aKc;
    const float* Bp = B + (size_t)bK * N + nBase + bCol;

    float acc[4][4][4];
#pragma unroll
    for (int mt = 0; mt < 4; mt++)
#pragma unroll
        for (int nt = 0; nt < 4; nt++)
#pragma unroll
            for (int f = 0; f < 4; f++) acc[mt][nt][f] = 0.f;

    // Prefetch first tile
    float4 pa0 = *(const float4*)(Ap);
    float4 pa1 = *(const float4*)(Ap + (size_t)64 * K);
    float4 pb0 = *(const float4*)(Bp);
    float4 pb1 = *(const float4*)(Bp + (size_t)8 * N);

    for (int k0 = 0; k0 < K; k0 += 16) {
        // Store prefetched tile to smem (A transposed [k][m], tf32-rounded)
        As[(aKc + 0) * LDS_ + aRow] = cvt_tf32(pa0.x);
        As[(aKc + 1) * LDS_ + aRow] = cvt_tf32(pa0.y);
        As[(aKc + 2) * LDS_ + aRow] = cvt_tf32(pa0.z);
        As[(aKc + 3) * LDS_ + aRow] = cvt_tf32(pa0.w);
        As[(aKc + 0) * LDS_ + aRow + 64] = cvt_tf32(pa1.x);
        As[(aKc + 1) * LDS_ + aRow + 64] = cvt_tf32(pa1.y);
        As[(aKc + 2) * LDS_ + aRow + 64] = cvt_tf32(pa1.z);
        As[(aKc + 3) * LDS_ + aRow + 64] = cvt_tf32(pa1.w);
        float4 cb0 = make_float4(cvt_tf32(pb0.x), cvt_tf32(pb0.y), cvt_tf32(pb0.z), cvt_tf32(pb0.w));
        float4 cb1 = make_float4(cvt_tf32(pb1.x), cvt_tf32(pb1.y), cvt_tf32(pb1.z), cvt_tf32(pb1.w));
        *(float4*)&Bs[(bK    ) * LDS_ + bCol] = cb0;
        *(float4*)&Bs[(bK + 8) * LDS_ + bCol] = cb1;
        __syncthreads();

        // Prefetch next tile while computing
        if (k0 + 16 < K) {
            pa0 = *(const float4*)(Ap + k0 + 16);
            pa1 = *(const float4*)(Ap + (size_t)64 * K + k0 + 16);
            pb0 = *(const float4*)(Bp + (size_t)(k0 + 16) * N);
            pb1 = *(const float4*)(Bp + (size_t)(k0 + 24) * N);
        }

#pragma unroll
        for (int ks = 0; ks < 16; ks += 8) {
            uint32_t af[4][4];
            uint32_t bf[4][2];
#pragma unroll
            for (int mt = 0; mt < 4; mt++) {
                const float* base = As + (ks + qd) * LDS_ + mWarp + mt * 16 + grp;
                af[mt][0] = __float_as_uint(base[0]);
                af[mt][1] = __float_as_uint(base[8]);
                af[mt][2] = __float_as_uint(base[4 * LDS_]);
                af[mt][3] = __float_as_uint(base[4 * LDS_ + 8]);
            }
#pragma unroll
            for (int nt = 0; nt < 4; nt++) {
                const float* base = Bs + (ks + qd) * LDS_ + nWarp + nt * 8 + grp;
                bf[nt][0] = __float_as_uint(base[0]);
                bf[nt][1] = __float_as_uint(base[4 * LDS_]);
            }
#pragma unroll
            for (int mt = 0; mt < 4; mt++)
#pragma unroll
                for (int nt = 0; nt < 4; nt++)
                    mma_tf32(acc[mt][nt], af[mt], bf[nt]);
        }
        __syncthreads();
    }

    // Epilogue: c0,c1 at (row, col..col+1); c2,c3 at (row+8, col..col+1)
#pragma unroll
    for (int mt = 0; mt < 4; mt++) {
#pragma unroll
        for (int nt = 0; nt < 4; nt++) {
            const int row = mBase + mWarp + mt * 16 + grp;
            const int col = nBase + nWarp + nt * 8 + qd * 2;
            const float b0 = bias[col], b1 = bias[col + 1];
#pragma unroll
            for (int rr = 0; rr < 2; rr++) {
                const int r = row + rr * 8;
                const size_t base = (size_t)r * N + col;
                float v0 = acc[mt][nt][rr * 2 + 0] + b0;
                float v1 = acc[mt][nt][rr * 2 + 1] + b1;
                if (GELU) {
                    v0 = 0.5f * v0 * (1.0f + erff(v0 * 0.70710678118654752f));
                    v1 = 0.5f * v1 * (1.0f + erff(v1 * 0.70710678118654752f));
                }
                if (HASRES) {
                    float2 rv = *(const float2*)(res + base);
                    v0 += rv.x; v1 += rv.y;
                }
                float2 o; o.x = v0; o.y = v1;
                *(float2*)(C + base) = o;
            }
        }
    }
}

// ---------------------------------------------------------------------------
// Chunked local attention (flash-style, fp32). One thread = one query row.
// ---------------------------------------------------------------------------
#define ATT_TK 16

__global__ __launch_bounds__(128) void attn_kernel(
    const float* __restrict__ qkv, const int* __restrict__ mask,
    float* __restrict__ out)
{
    const int blk = blockIdx.x;
    const int qt  = blk & 3;
    const int c   = (blk >> 2) & 3;
    const int bh  = blk >> 4;               // 0..31
    const int b   = bh >> 3;
    const int h   = bh & 7;
    const int tid = threadIdx.x;
    const int lq  = c * SCHUNK + qt * 128 + tid;

    const float* qrow = qkv + ((size_t)(b * LSEQ + lq)) * QKV3 + h * HDIM;
    float q[HDIM];
#pragma unroll
    for (int d4 = 0; d4 < 16; d4++) {
        float4 v = *(const float4*)(qrow + d4 * 4);
        q[d4 * 4 + 0] = v.x * 0.125f;
        q[d4 * 4 + 1] = v.y * 0.125f;
        q[d4 * 4 + 2] = v.z * 0.125f;
        q[d4 * 4 + 3] = v.w * 0.125f;
    }

    float acc[HDIM];
#pragma unroll
    for (int d = 0; d < HDIM; d++) acc[d] = 0.f;
    float mrun = -1e30f, lrun = 0.f;

    __shared__ float ks[ATT_TK][HDIM];
    __shared__ float vs[ATT_TK][HDIM];
    __shared__ int   msk[ATT_TK];

    int k0 = (c - 1) * SCHUNK; if (k0 < 0) k0 = 0;
    int k1 = (c + 2) * SCHUNK; if (k1 > LSEQ) k1 = LSEQ;

    for (int kt = k0; kt < k1; kt += ATT_TK) {
        __syncthreads();
#pragma unroll
        for (int r = 0; r < 2; r++) {
            const int fi = tid + r * 128;
            const int j  = fi >> 4;
            const int d4 = fi & 15;
            const float* kp = qkv + ((size_t)(b * LSEQ + kt + j)) * QKV3
                              + DMODEL + h * HDIM + d4 * 4;
            *(float4*)&ks[j][d4 * 4] = *(const float4*)kp;
            *(float4*)&vs[j][d4 * 4] = *(const float4*)(kp + DMODEL);
        }
        if (tid < ATT_TK) msk[tid] = mask[b * LSEQ + kt + tid];
        __syncthreads();

        float s[ATT_TK];
        float tmax = -1e30f;
#pragma unroll
        for (int j = 0; j < ATT_TK; j++) {
            float dot = 0.f;
#pragma unroll
            for (int d4 = 0; d4 < 16; d4++) {
                float4 kv = *(const float4*)&ks[j][d4 * 4];
                dot += q[d4 * 4 + 0] * kv.x;
                dot += q[d4 * 4 + 1] * kv.y;
                dot += q[d4 * 4 + 2] * kv.z;
                dot += q[d4 * 4 + 3] * kv.w;
            }
            s[j] = msk[j] ? -1e30f : dot;
            tmax = fmaxf(tmax, s[j]);
        }

        const float mnew  = fmaxf(mrun, tmax);
        const float scale = __expf(mrun - mnew);
        lrun *= scale;
#pragma unroll
        for (int d = 0; d < HDIM; d++) acc[d] *= scale;
        mrun = mnew;

#pragma unroll
        for (int j = 0; j < ATT_TK; j++) {
            const float p = __expf(s[j] - mnew);
            lrun += p;
#pragma unroll
            for (int d4 = 0; d4 < 16; d4++) {
                float4 vv = *(const float4*)&vs[j][d4 * 4];
                acc[d4 * 4 + 0] += p * vv.x;
                acc[d4 * 4 + 1] += p * vv.y;
                acc[d4 * 4 + 2] += p * vv.z;
                acc[d4 * 4 + 3] += p * vv.w;
            }
        }
    }

    const float invl = 1.0f / lrun;
    float* op = out + ((size_t)(b * LSEQ + lq)) * DMODEL + h * HDIM;
#pragma unroll
    for (int d4 = 0; d4 < 16; d4++) {
        float4 o;
        o.x = acc[d4 * 4 + 0] * invl;
        o.y = acc[d4 * 4 + 1] * invl;
        o.z = acc[d4 * 4 + 2] * invl;
        o.w = acc[d4 * 4 + 3] * invl;
        *(float4*)(op + d4 * 4) = o;
    }
}

// ---------------------------------------------------------------------------
// LayerNorm over last dim (512). One block per row, 128 threads x float4.
// ---------------------------------------------------------------------------
__global__ __launch_bounds__(128) void ln_kernel(
    const float* __restrict__ in, const float* __restrict__ gg,
    const float* __restrict__ bb, float* __restrict__ out)
{
    const int row = blockIdx.x, tid = threadIdx.x;
    const float* p = in + (size_t)row * DMODEL;
    float4 v = *(const float4*)(p + tid * 4);
    float s  = v.x + v.y + v.z + v.w;
    float ss = v.x * v.x + v.y * v.y + v.z * v.z + v.w * v.w;
#pragma unroll
    for (int o = 16; o > 0; o >>= 1) {
        s  += __shfl_xor_sync(0xffffffffu, s,  o);
        ss += __shfl_xor_sync(0xffffffffu, ss, o);
    }
    __shared__ float sh[8];
    const int w = tid >> 5, ln = tid & 31;
    if (ln == 0) { sh[w] = s; sh[4 + w] = ss; }
    __syncthreads();
    s  = sh[0] + sh[1] + sh[2] + sh[3];
    ss = sh[4] + sh[5] + sh[6] + sh[7];
    const float mu  = s * (1.0f / DMODEL);
    const float var = ss * (1.0f / DMODEL) - mu * mu;
    const float inv = rsqrtf(var + 1e-5f);
    float4 gv = *(const float4*)(gg + tid * 4);
    float4 bv = *(const float4*)(bb + tid * 4);
    float4 o4;
    o4.x = (v.x - mu) * inv * gv.x + bv.x;
    o4.y = (v.y - mu) * inv * gv.y + bv.y;
    o4.z = (v.z - mu) * inv * gv.z + bv.z;
    o4.w = (v.w - mu) * inv * gv.w + bv.w;
    *(float4*)(out + (size_t)row * DMODEL + tid * 4) = o4;
}

// ---------------------------------------------------------------------------
extern "C" void kernel_launch(void* const* d_in, const int* in_sizes, int n_in,
                              void* d_out, int out_size)
{
    const float* x      = (const float*)d_in[0];
    const int*   mask   = (const int*)  d_in[1];
    const float* qkv_w  = (const float*)d_in[2];
    const float* qkv_b  = (const float*)d_in[3];
    const float* out_w  = (const float*)d_in[4];
    const float* out_b  = (const float*)d_in[5];
    const float* ffn_w1 = (const float*)d_in[6];
    const float* ffn_b1 = (const float*)d_in[7];
    const float* ffn_w2 = (const float*)d_in[8];
    const float* ffn_b2 = (const float*)d_in[9];
    const float* ln1_g  = (const float*)d_in[10];
    const float* ln1_b  = (const float*)d_in[11];
    const float* ln2_g  = (const float*)d_in[12];
    const float* ln2_b  = (const float*)d_in[13];
    float* out = (float*)d_out;

    float *qkvp, *attnp, *x1p, *ffnp;
    cudaGetSymbolAddress((void**)&qkvp,  g_qkv);
    cudaGetSymbolAddress((void**)&attnp, g_attn);
    cudaGetSymbolAddress((void**)&x1p,   g_x1);
    cudaGetSymbolAddress((void**)&ffnp,  g_ffn);

    // 1) QKV = X @ qkv_w + qkv_b                      [8192,1536]
    tgemm_kernel<0,0><<<dim3(QKV3 / 128, BL / 128), 256>>>(
        x, qkv_w, qkv_b, nullptr, qkvp, BL, QKV3, DMODEL);

    // 2) Chunked local attention -> merged [B,L,D]
    attn_kernel<<<512, 128>>>(qkvp, mask, attnp);

    // 3) pre1 = x + (attn @ out_w + out_b)            [8192,512]
    tgemm_kernel<0,1><<<dim3(DMODEL / 128, BL / 128), 256>>>(
        attnp, out_w, out_b, x, x1p, BL, DMODEL, DMODEL);

    // 4) x1 = LN1(pre1)  (in-place)
    ln_kernel<<<BL, 128>>>(x1p, ln1_g, ln1_b, x1p);

    // 5) h = gelu(x1 @ ffn_w1 + ffn_b1)               [8192,2048]
    tgemm_kernel<1,0><<<dim3(FFND / 128, BL / 128), 256>>>(
        x1p, ffn_w1, ffn_b1, nullptr, ffnp, BL, FFND, DMODEL);

    // 6) pre2 = x1 + (h @ ffn_w2 + ffn_b2)            [8192,512] (reuse g_attn)
    tgemm_kernel<0,1><<<dim3(DMODEL / 128, BL / 128), 256>>>(
        ffnp, ffn_w2, ffn_b2, x1p, attnp, BL, DMODEL, FFND);

    // 7) out = LN2(pre2)
    ln_kernel<<<BL, 128>>>(attnp, ln2_g, ln2_b, out);
}

// round 3
// speedup vs baseline: 4.0827x; 2.8210x over previous
#include <cuda_runtime.h>
#include <math.h>
#include <stdint.h>

#define BQ      4
#define LSEQ    2048
#define DMODEL  512
#define NHEAD   8
#define HDIM    64
#define FFND    2048
#define BL      (BQ * LSEQ)
#define QKV3    (3 * DMODEL)
#define SCHUNK  512

__device__ float g_qkv [BL * QKV3];
__device__ float g_attn[BL * DMODEL];
__device__ float g_x1  [BL * DMODEL];
__device__ float g_ffn [BL * FFND];

__device__ __forceinline__ float cvt_tf32(float x) {
    uint32_t u;
    asm("cvt.rna.tf32.f32 %0, %1;" : "=r"(u) : "f"(x));
    return __uint_as_float(u);
}

__device__ __forceinline__ void mma_tf32(float* d, const float* a, const float* b) {
    asm volatile(
        "mma.sync.aligned.m16n8k8.row.col.f32.tf32.tf32.f32 "
        "{%0,%1,%2,%3}, {%4,%5,%6,%7}, {%8,%9}, {%0,%1,%2,%3};"
        : "+f"(d[0]), "+f"(d[1]), "+f"(d[2]), "+f"(d[3])
        : "r"(__float_as_uint(a[0])), "r"(__float_as_uint(a[1])),
          "r"(__float_as_uint(a[2])), "r"(__float_as_uint(a[3])),
          "r"(__float_as_uint(b[0])), "r"(__float_as_uint(b[1])));
}

__device__ __forceinline__ uint32_t smaddr(const void* p) {
    uint32_t a;
    asm("{.reg .u64 t; cvta.to.shared.u64 t, %1; cvt.u32.u64 %0, t;}" : "=r"(a) : "l"(p));
    return a;
}
#define CP16(dst, src) asm volatile("cp.async.cg.shared.global [%0], [%1], 16;" :: "r"(dst), "l"(src))
#define CPCOMMIT()     asm volatile("cp.async.commit_group;")
#define CPWAIT(n)      asm volatile("cp.async.wait_group %0;" :: "n"(n))

// ---------------------------------------------------------------------------
// TF32 GEMM, cp.async 2-stage pipeline. Block 128x128xBK16, 256 thr, 8 warps
// (2M x 4N), warp tile 64x32. A smem [m][k] stride 20; B smem [k][n] stride
// 136 (both conflict-free for fragment loads). tf32 rna-convert at frag load.
// ---------------------------------------------------------------------------
#define LDA_ 20
#define LDB_ 136

template<int GELU, int HASRES>
__global__ __launch_bounds__(256, 2) void tgemm_kernel(
    const float* __restrict__ A, const float* __restrict__ B,
    const float* __restrict__ bias, const float* __restrict__ res,
    float* __restrict__ C, int M, int N, int K)
{
    __shared__ float As[2][128 * LDA_];
    __shared__ float Bs[2][16 * LDB_];

    const int tid   = threadIdx.x;
    const int mBase = blockIdx.y * 128;
    const int nBase = blockIdx.x * 128;
    const int lane  = tid & 31, wid = tid >> 5;
    const int grp   = lane >> 2, qd = lane & 3;
    const int mWarp = (wid & 1) * 64;
    const int nWarp = (wid >> 1) * 32;

    const int aRow = tid >> 2;           // 0..63 (+64 second)
    const int aKc  = (tid & 3) * 4;
    const int bK   = tid >> 5;           // 0..7 (+8 second)
    const int bCol = (tid & 31) * 4;

    const float* Ap = A + (size_t)(mBase + aRow) * K + aKc;
    const float* Bp = B + (size_t)bK * N + nBase + bCol;

    const uint32_t sA0 = smaddr(&As[0][aRow * LDA_ + aKc]);
    const uint32_t sA1 = smaddr(&As[1][aRow * LDA_ + aKc]);
    const uint32_t sB0 = smaddr(&Bs[0][bK * LDB_ + bCol]);
    const uint32_t sB1 = smaddr(&Bs[1][bK * LDB_ + bCol]);

    float acc[4][4][4];
#pragma unroll
    for (int mt = 0; mt < 4; mt++)
#pragma unroll
        for (int nt = 0; nt < 4; nt++)
#pragma unroll
            for (int f = 0; f < 4; f++) acc[mt][nt][f] = 0.f;

    const int niter = K >> 4;

    // prologue: stage 0 copies
    {
        CP16(sA0, Ap);
        CP16(sA0 + 64 * LDA_ * 4, Ap + (size_t)64 * K);
        CP16(sB0, Bp);
        CP16(sB0 + 8 * LDB_ * 4, Bp + (size_t)8 * N);
        CPCOMMIT();
    }

    for (int it = 0; it < niter; it++) {
        if (it + 1 < niter) {
            const int k0 = (it + 1) << 4;
            const uint32_t dA = ((it + 1) & 1) ? sA1 : sA0;
            const uint32_t dB = ((it + 1) & 1) ? sB1 : sB0;
            CP16(dA, Ap + k0);
            CP16(dA + 64 * LDA_ * 4, Ap + (size_t)64 * K + k0);
            CP16(dB, Bp + (size_t)k0 * N);
            CP16(dB + 8 * LDB_ * 4, Bp + (size_t)(k0 + 8) * N);
            CPCOMMIT();
            CPWAIT(1);
        } else {
            CPWAIT(0);
        }
        __syncthreads();

        const float* Ac = As[it & 1];
        const float* Bc = Bs[it & 1];
#pragma unroll
        for (int ks = 0; ks < 16; ks += 8) {
            float af[4][4];
            float bf[4][2];
#pragma unroll
            for (int mt = 0; mt < 4; mt++) {
                const float* base = Ac + (mWarp + mt * 16 + grp) * LDA_ + ks + qd;
                af[mt][0] = cvt_tf32(base[0]);
                af[mt][1] = cvt_tf32(base[8 * LDA_]);
                af[mt][2] = cvt_tf32(base[4]);
                af[mt][3] = cvt_tf32(base[8 * LDA_ + 4]);
            }
#pragma unroll
            for (int nt = 0; nt < 4; nt++) {
                const float* base = Bc + (ks + qd) * LDB_ + nWarp + nt * 8 + grp;
                bf[nt][0] = cvt_tf32(base[0]);
                bf[nt][1] = cvt_tf32(base[4 * LDB_]);
            }
#pragma unroll
            for (int mt = 0; mt < 4; mt++)
#pragma unroll
                for (int nt = 0; nt < 4; nt++)
                    mma_tf32(acc[mt][nt], af[mt], bf[nt]);
        }
        __syncthreads();
    }

#pragma unroll
    for (int mt = 0; mt < 4; mt++) {
#pragma unroll
        for (int nt = 0; nt < 4; nt++) {
            const int row = mBase + mWarp + mt * 16 + grp;
            const int col = nBase + nWarp + nt * 8 + qd * 2;
            const float b0 = bias[col], b1 = bias[col + 1];
#pragma unroll
            for (int rr = 0; rr < 2; rr++) {
                const int r = row + rr * 8;
                const size_t base = (size_t)r * N + col;
                float v0 = acc[mt][nt][rr * 2 + 0] + b0;
                float v1 = acc[mt][nt][rr * 2 + 1] + b1;
                if (GELU) {
                    v0 = 0.5f * v0 * (1.0f + erff(v0 * 0.70710678118654752f));
                    v1 = 0.5f * v1 * (1.0f + erff(v1 * 0.70710678118654752f));
                }
                if (HASRES) {
                    float2 rv = *(const float2*)(res + base);
                    v0 += rv.x; v1 += rv.y;
                }
                float2 o; o.x = v0; o.y = v1;
                *(float2*)(C + base) = o;
            }
        }
    }
}

// ---------------------------------------------------------------------------
// Tensor-core flash attention. Block = (b,h,chunk,qtile): 4 warps x 32 q rows
// = 128 q. Key tiles of 32. QK^T and PV via m16n8k8 tf32. Row softmax with
// quad shuffles; P round-trips per-warp smem scratch.
// ---------------------------------------------------------------------------
#define LDK_ 68
#define LDV_ 36
#define LDP_ 36

__device__ __forceinline__ float qmax4(float v) {
    v = fmaxf(v, __shfl_xor_sync(0xffffffffu, v, 1));
    v = fmaxf(v, __shfl_xor_sync(0xffffffffu, v, 2));
    return v;
}
__device__ __forceinline__ float qsum4(float v) {
    v += __shfl_xor_sync(0xffffffffu, v, 1);
    v += __shfl_xor_sync(0xffffffffu, v, 2);
    return v;
}

__global__ __launch_bounds__(128, 2) void attn_mma_kernel(
    const float* __restrict__ qkv, const int* __restrict__ mask,
    float* __restrict__ out)
{
    __shared__ float Ks[32 * LDK_];
    __shared__ float Vs[64 * LDV_];
    __shared__ float Ps[4][32 * LDP_];
    __shared__ float biasS[32];

    const int blk = blockIdx.x;
    const int qt  = blk & 3;
    const int c   = (blk >> 2) & 3;
    const int bh  = blk >> 4;
    const int b   = bh >> 3, h = bh & 7;
    const int tid = threadIdx.x, lane = tid & 31, wid = tid >> 5;
    const int grp = lane >> 2, qd = lane & 3;
    const int lq0 = c * SCHUNK + qt * 128 + wid * 32;

    // Q a-frags (pre-scaled by 1/sqrt(HD), rna tf32)
    float qa[2][8][4];
#pragma unroll
    for (int mt = 0; mt < 2; mt++)
#pragma unroll
        for (int kk = 0; kk < 8; kk++) {
            const float* q0 = qkv + (size_t)(b * LSEQ + lq0 + mt * 16 + grp) * QKV3
                              + h * HDIM + kk * 8 + qd;
            const float* q1 = q0 + (size_t)8 * QKV3;
            qa[mt][kk][0] = cvt_tf32(q0[0] * 0.125f);
            qa[mt][kk][1] = cvt_tf32(q1[0] * 0.125f);
            qa[mt][kk][2] = cvt_tf32(q0[4] * 0.125f);
            qa[mt][kk][3] = cvt_tf32(q1[4] * 0.125f);
        }

    float O[2][8][4];
#pragma unroll
    for (int mt = 0; mt < 2; mt++)
#pragma unroll
        for (int nt = 0; nt < 8; nt++)
#pragma unroll
            for (int f = 0; f < 4; f++) O[mt][nt][f] = 0.f;
    float mrow[2][2] = {{-1e30f, -1e30f}, {-1e30f, -1e30f}};
    float lrow[2][2] = {{0.f, 0.f}, {0.f, 0.f}};

    int k0 = (c - 1) * SCHUNK; if (k0 < 0) k0 = 0;
    int k1 = (c + 2) * SCHUNK; if (k1 > LSEQ) k1 = LSEQ;

    float* Pw = Ps[wid];

    for (int kt = k0; kt < k1; kt += 32) {
        __syncthreads();
        // Stage K [32 keys][64 d] and V transposed [64 d][32 keys]
#pragma unroll
        for (int p = 0; p < 4; p++) {
            const int fi  = p * 128 + tid;
            const int row = fi >> 4;
            const int d4  = fi & 15;
            const float* kp = qkv + (size_t)(b * LSEQ + kt + row) * QKV3
                              + DMODEL + h * HDIM + d4 * 4;
            float4 kv = *(const float4*)kp;
            float4 ck = make_float4(cvt_tf32(kv.x), cvt_tf32(kv.y), cvt_tf32(kv.z), cvt_tf32(kv.w));
            *(float4*)&Ks[row * LDK_ + d4 * 4] = ck;
            float4 vv = *(const float4*)(kp + DMODEL);
            Vs[(d4 * 4 + 0) * LDV_ + row] = cvt_tf32(vv.x);
            Vs[(d4 * 4 + 1) * LDV_ + row] = cvt_tf32(vv.y);
            Vs[(d4 * 4 + 2) * LDV_ + row] = cvt_tf32(vv.z);
            Vs[(d4 * 4 + 3) * LDV_ + row] = cvt_tf32(vv.w);
        }
        if (tid < 32) biasS[tid] = mask[b * LSEQ + kt + tid] ? -1e30f : 0.f;
        __syncthreads();

        // S = Q K^T : [32 q x 32 keys] per warp
        float sc[2][4][4];
#pragma unroll
        for (int mt = 0; mt < 2; mt++)
#pragma unroll
            for (int nt = 0; nt < 4; nt++)
#pragma unroll
                for (int f = 0; f < 4; f++) sc[mt][nt][f] = 0.f;
#pragma unroll
        for (int kk = 0; kk < 8; kk++) {
            float kb[4][2];
#pragma unroll
            for (int nt = 0; nt < 4; nt++) {
                const float* kbase = Ks + (nt * 8 + grp) * LDK_ + kk * 8 + qd;
                kb[nt][0] = kbase[0];
                kb[nt][1] = kbase[4];
            }
#pragma unroll
            for (int mt = 0; mt < 2; mt++)
#pragma unroll
                for (int nt = 0; nt < 4; nt++)
                    mma_tf32(sc[mt][nt], qa[mt][kk], kb[nt]);
        }

        // Softmax (rows grp, grp+8 per mt; spread over quad lanes)
        float bs0[4], bs1[4];
#pragma unroll
        for (int nt = 0; nt < 4; nt++) {
            bs0[nt] = biasS[nt * 8 + 2 * qd];
            bs1[nt] = biasS[nt * 8 + 2 * qd + 1];
        }
        float scl[2][2];
#pragma unroll
        for (int mt = 0; mt < 2; mt++) {
            float nm0 = -1e30f, nm1 = -1e30f;
#pragma unroll
            for (int nt = 0; nt < 4; nt++) {
                nm0 = fmaxf(nm0, fmaxf(sc[mt][nt][0] + bs0[nt], sc[mt][nt][1] + bs1[nt]));
                nm1 = fmaxf(nm1, fmaxf(sc[mt][nt][2] + bs0[nt], sc[mt][nt][3] + bs1[nt]));
            }
            nm0 = qmax4(nm0); nm1 = qmax4(nm1);
            const float m0 = fmaxf(mrow[mt][0], nm0);
            const float m1 = fmaxf(mrow[mt][1], nm1);
            scl[mt][0] = __expf(mrow[mt][0] - m0);
            scl[mt][1] = __expf(mrow[mt][1] - m1);
            lrow[mt][0] *= scl[mt][0];
            lrow[mt][1] *= scl[mt][1];
            mrow[mt][0] = m0; mrow[mt][1] = m1;
        }
#pragma unroll
        for (int mt = 0; mt < 2; mt++)
#pragma unroll
            for (int nt = 0; nt < 8; nt++) {
                O[mt][nt][0] *= scl[mt][0];
                O[mt][nt][1] *= scl[mt][0];
                O[mt][nt][2] *= scl[mt][1];
                O[mt][nt][3] *= scl[mt][1];
            }
        float rs[2][2] = {{0.f, 0.f}, {0.f, 0.f}};
#pragma unroll
        for (int mt = 0; mt < 2; mt++)
#pragma unroll
            for (int nt = 0; nt < 4; nt++) {
                float p0 = cvt_tf32(__expf(sc[mt][nt][0] + bs0[nt] - mrow[mt][0]));
                float p1 = cvt_tf32(__expf(sc[mt][nt][1] + bs1[nt] - mrow[mt][0]));
                float p2 = cvt_tf32(__expf(sc[mt][nt][2] + bs0[nt] - mrow[mt][1]));
                float p3 = cvt_tf32(__expf(sc[mt][nt][3] + bs1[nt] - mrow[mt][1]));
                rs[mt][0] += p0 + p1;
                rs[mt][1] += p2 + p3;
                float2 w0; w0.x = p0; w0.y = p1;
                float2 w1; w1.x = p2; w1.y = p3;
                *(float2*)&Pw[(mt * 16 + grp)     * LDP_ + nt * 8 + 2 * qd] = w0;
                *(float2*)&Pw[(mt * 16 + grp + 8) * LDP_ + nt * 8 + 2 * qd] = w1;
            }
#pragma unroll
        for (int mt = 0; mt < 2; mt++) {
            lrow[mt][0] += qsum4(rs[mt][0]);
            lrow[mt][1] += qsum4(rs[mt][1]);
        }
        __syncwarp();

        // O += P V  (k = 32 keys)
#pragma unroll
        for (int kk = 0; kk < 4; kk++) {
            float pa[2][4];
#pragma unroll
            for (int mt = 0; mt < 2; mt++) {
                const float* base = Pw + (mt * 16 + grp) * LDP_ + kk * 8 + qd;
                pa[mt][0] = base[0];
                pa[mt][1] = base[8 * LDP_];
                pa[mt][2] = base[4];
                pa[mt][3] = base[8 * LDP_ + 4];
            }
            float vb[8][2];
#pragma unroll
            for (int nt = 0; nt < 8; nt++) {
                const float* vbase = Vs + (nt * 8 + grp) * LDV_ + kk * 8 + qd;
                vb[nt][0] = vbase[0];
                vb[nt][1] = vbase[4];
            }
#pragma unroll
            for (int mt = 0; mt < 2; mt++)
#pragma unroll
                for (int nt = 0; nt < 8; nt++)
                    mma_tf32(O[mt][nt], pa[mt], vb[nt]);
        }
        __syncwarp();
    }

    // Epilogue: normalize and store to merged [B,L,D]
#pragma unroll
    for (int mt = 0; mt < 2; mt++) {
        const float inv0 = 1.0f / lrow[mt][0];
        const float inv1 = 1.0f / lrow[mt][1];
#pragma unroll
        for (int nt = 0; nt < 8; nt++) {
            const int row = lq0 + mt * 16 + grp;
            const int col = h * HDIM + nt * 8 + 2 * qd;
            float2 o0; o0.x = O[mt][nt][0] * inv0; o0.y = O[mt][nt][1] * inv0;
            float2 o1; o1.x = O[mt][nt][2] * inv1; o1.y = O[mt][nt][3] * inv1;
            *(float2*)(out + (size_t)(b * LSEQ + row) * DMODEL + col) = o0;
            *(float2*)(out + (size_t)(b * LSEQ + row + 8) * DMODEL + col) = o1;
        }
    }
}

// ---------------------------------------------------------------------------
__global__ __launch_bounds__(128) void ln_kernel(
    const float* __restrict__ in, const float* __restrict__ gg,
    const float* __restrict__ bb, float* __restrict__ out)
{
    const int row = blockIdx.x, tid = threadIdx.x;
    const float* p = in + (size_t)row * DMODEL;
    float4 v = *(const float4*)(p + tid * 4);
    float s  = v.x + v.y + v.z + v.w;
    float ss = v.x * v.x + v.y * v.y + v.z * v.z + v.w * v.w;
#pragma unroll
    for (int o = 16; o > 0; o >>= 1) {
        s  += __shfl_xor_sync(0xffffffffu, s,  o);
        ss += __shfl_xor_sync(0xffffffffu, ss, o);
    }
    __shared__ float sh[8];
    const int w = tid >> 5, ln = tid & 31;
    if (ln == 0) { sh[w] = s; sh[4 + w] = ss; }
    __syncthreads();
    s  = sh[0] + sh[1] + sh[2] + sh[3];
    ss = sh[4] + sh[5] + sh[6] + sh[7];
    const float mu  = s * (1.0f / DMODEL);
    const float var = ss * (1.0f / DMODEL) - mu * mu;
    const float inv = rsqrtf(var + 1e-5f);
    float4 gv = *(const float4*)(gg + tid * 4);
    float4 bv = *(const float4*)(bb + tid * 4);
    float4 o4;
    o4.x = (v.x - mu) * inv * gv.x + bv.x;
    o4.y = (v.y - mu) * inv * gv.y + bv.y;
    o4.z = (v.z - mu) * inv * gv.z + bv.z;
    o4.w = (v.w - mu) * inv * gv.w + bv.w;
    *(float4*)(out + (size_t)row * DMODEL + tid * 4) = o4;
}

// ---------------------------------------------------------------------------
extern "C" void kernel_launch(void* const* d_in, const int* in_sizes, int n_in,
                              void* d_out, int out_size)
{
    const float* x      = (const float*)d_in[0];
    const int*   mask   = (const int*)  d_in[1];
    const float* qkv_w  = (const float*)d_in[2];
    const float* qkv_b  = (const float*)d_in[3];
    const float* out_w  = (const float*)d_in[4];
    const float* out_b  = (const float*)d_in[5];
    const float* ffn_w1 = (const float*)d_in[6];
    const float* ffn_b1 = (const float*)d_in[7];
    const float* ffn_w2 = (const float*)d_in[8];
    const float* ffn_b2 = (const float*)d_in[9];
    const float* ln1_g  = (const float*)d_in[10];
    const float* ln1_b  = (const float*)d_in[11];
    const float* ln2_g  = (const float*)d_in[12];
    const float* ln2_b  = (const float*)d_in[13];
    float* out = (float*)d_out;

    float *qkvp, *attnp, *x1p, *ffnp;
    cudaGetSymbolAddress((void**)&qkvp,  g_qkv);
    cudaGetSymbolAddress((void**)&attnp, g_attn);
    cudaGetSymbolAddress((void**)&x1p,   g_x1);
    cudaGetSymbolAddress((void**)&ffnp,  g_ffn);

    // 1) QKV = X @ qkv_w + qkv_b
    tgemm_kernel<0,0><<<dim3(QKV3 / 128, BL / 128), 256>>>(
        x, qkv_w, qkv_b, nullptr, qkvp, BL, QKV3, DMODEL);

    // 2) Tensor-core chunked local attention -> merged [B,L,D]
    attn_mma_kernel<<<512, 128>>>(qkvp, mask, attnp);

    // 3) pre1 = x + (attn @ out_w + out_b)
    tgemm_kernel<0,1><<<dim3(DMODEL / 128, BL / 128), 256>>>(
        attnp, out_w, out_b, x, x1p, BL, DMODEL, DMODEL);

    // 4) x1 = LN1(pre1)
    ln_kernel<<<BL, 128>>>(x1p, ln1_g, ln1_b, x1p);

    // 5) h = gelu(x1 @ ffn_w1 + ffn_b1)
    tgemm_kernel<1,0><<<dim3(FFND / 128, BL / 128), 256>>>(
        x1p, ffn_w1, ffn_b1, nullptr, ffnp, BL, FFND, DMODEL);

    // 6) pre2 = x1 + (h @ ffn_w2 + ffn_b2)
    tgemm_kernel<0,1><<<dim3(DMODEL / 128, BL / 128), 256>>>(
        ffnp, ffn_w2, ffn_b2, x1p, attnp, BL, DMODEL, FFND);

    // 7) out = LN2(pre2)
    ln_kernel<<<BL, 128>>>(attnp, ln2_g, ln2_b, out);
}

// round 5
// speedup vs baseline: 6.1498x; 1.5063x over previous
#include <cuda_runtime.h>
#include <cuda_fp16.h>
#include <math.h>
#include <stdint.h>

#define BQ      4
#define LSEQ    2048
#define DMODEL  512
#define NHEAD   8
#define HDIM    64
#define FFND    2048
#define BL      (BQ * LSEQ)
#define QKV3    (3 * DMODEL)
#define SCHUNK  512

// Scratch (static device globals)
__device__ __half g_qkvh [BL * QKV3];    // GEMM1 out (half)
__device__ __half g_attnh[BL * DMODEL];  // attention out (half)
__device__ __half g_ffnh [BL * FFND];    // GEMM3 out (half)
__device__ __half g_xh   [BL * DMODEL];  // x as half
__device__ __half g_x1h  [BL * DMODEL];  // LN1 out half
__device__ float  g_x1   [BL * DMODEL];  // LN1 out f32
__device__ float  g_pre  [BL * DMODEL];  // pre-LN buffer (f32)
// Transposed ([N][K]) half weights
__device__ __half g_qkvwT[QKV3 * DMODEL];
__device__ __half g_outwT[DMODEL * DMODEL];
__device__ __half g_ffn1T[FFND * DMODEL];
__device__ __half g_ffn2T[DMODEL * FFND];

// ---------------------------------------------------------------------------
__device__ __forceinline__ void mma_f16(float* d, const uint32_t* a, const uint32_t* b) {
    asm volatile(
        "mma.sync.aligned.m16n8k16.row.col.f32.f16.f16.f32 "
        "{%0,%1,%2,%3}, {%4,%5,%6,%7}, {%8,%9}, {%0,%1,%2,%3};"
        : "+f"(d[0]), "+f"(d[1]), "+f"(d[2]), "+f"(d[3])
        : "r"(a[0]), "r"(a[1]), "r"(a[2]), "r"(a[3]), "r"(b[0]), "r"(b[1]));
}
__device__ __forceinline__ uint32_t smaddr(const void* p) {
    uint32_t a;
    asm("{.reg .u64 t; cvta.to.shared.u64 t, %1; cvt.u32.u64 %0, t;}" : "=r"(a) : "l"(p));
    return a;
}
#define CP16(dst, src) asm volatile("cp.async.cg.shared.global [%0], [%1], 16;" :: "r"(dst), "l"(src))
#define CPCOMMIT()     asm volatile("cp.async.commit_group;")
#define CPWAIT(n)      asm volatile("cp.async.wait_group %0;" :: "n"(n))

// ---------------------------------------------------------------------------
// FP16 tensor GEMM: C[M,N] = A[M,K] @ BT[N,K]^T (+bias)(GELU?)(+res f32?)
// A,BT half. Block 128x128, BK=32, 256 thr = 8 warps (2M x 4N), warp 64x32,
// m16n8k16 frags. Smem strides 40 halves (conflict-free). cp.async 2-stage.
// OUTH: write half to Ch; else write float to Cf.
// ---------------------------------------------------------------------------
#define LDA_ 40
#define LDB_ 40

template<int GELU, int HASRES, int OUTH>
__global__ __launch_bounds__(256, 2) void hgemm_kernel(
    const __half* __restrict__ A, const __half* __restrict__ BT,
    const float* __restrict__ bias, const float* __restrict__ res,
    __half* __restrict__ Ch, float* __restrict__ Cf, int M, int N, int K)
{
    __shared__ __half As[2][128 * LDA_];
    __shared__ __half Bs[2][128 * LDB_];

    const int tid   = threadIdx.x;
    const int lane  = tid & 31, wid = tid >> 5;
    const int grp   = lane >> 2, qd = lane & 3;
    const int mBase = blockIdx.y * 128;
    const int nBase = blockIdx.x * 128;
    const int mWarp = (wid & 1) * 64;
    const int nWarp = (wid >> 1) * 32;

    // staging mapping: c = tid + i*256 (0..511): row = c>>2, seg = (c&3)*8 halves
    const int sRow0 = tid >> 2,        sSeg0 = (tid & 3) * 8;
    const int sRow1 = (tid + 256) >> 2, sSeg1 = ((tid + 256) & 3) * 8;

    const __half* Ap0 = A  + (size_t)(mBase + sRow0) * K + sSeg0;
    const __half* Ap1 = A  + (size_t)(mBase + sRow1) * K + sSeg1;
    const __half* Bp0 = BT + (size_t)(nBase + sRow0) * K + sSeg0;
    const __half* Bp1 = BT + (size_t)(nBase + sRow1) * K + sSeg1;

    const uint32_t sA[2] = { smaddr(&As[0][sRow0 * LDA_ + sSeg0]), smaddr(&As[1][sRow0 * LDA_ + sSeg0]) };
    const uint32_t sA2[2]= { smaddr(&As[0][sRow1 * LDA_ + sSeg1]), smaddr(&As[1][sRow1 * LDA_ + sSeg1]) };
    const uint32_t sB[2] = { smaddr(&Bs[0][sRow0 * LDB_ + sSeg0]), smaddr(&Bs[1][sRow0 * LDB_ + sSeg0]) };
    const uint32_t sB2[2]= { smaddr(&Bs[0][sRow1 * LDB_ + sSeg1]), smaddr(&Bs[1][sRow1 * LDB_ + sSeg1]) };

    float acc[4][4][4];
#pragma unroll
    for (int mt = 0; mt < 4; mt++)
#pragma unroll
        for (int nt = 0; nt < 4; nt++)
#pragma unroll
            for (int f = 0; f < 4; f++) acc[mt][nt][f] = 0.f;

    const int niter = K >> 5;

    // prologue
    CP16(sA[0], Ap0); CP16(sA2[0], Ap1);
    CP16(sB[0], Bp0); CP16(sB2[0], Bp1);
    CPCOMMIT();

    for (int it = 0; it < niter; it++) {
        const int buf = it & 1;
        if (it + 1 < niter) {
            const int k0 = (it + 1) << 5;
            CP16(sA[buf ^ 1], Ap0 + k0); CP16(sA2[buf ^ 1], Ap1 + k0);
            CP16(sB[buf ^ 1], Bp0 + k0); CP16(sB2[buf ^ 1], Bp1 + k0);
            CPCOMMIT();
            CPWAIT(1);
        } else {
            CPWAIT(0);
        }
        __syncthreads();

        const __half* Ac = As[buf];
        const __half* Bc = Bs[buf];
#pragma unroll
        for (int ks = 0; ks < 32; ks += 16) {
            uint32_t af[4][4], bf[4][2];
#pragma unroll
            for (int mt = 0; mt < 4; mt++) {
                const __half* base = Ac + (mWarp + mt * 16 + grp) * LDA_ + ks + 2 * qd;
                af[mt][0] = *(const uint32_t*)(base);
                af[mt][1] = *(const uint32_t*)(base + 8 * LDA_);
                af[mt][2] = *(const uint32_t*)(base + 8);
                af[mt][3] = *(const uint32_t*)(base + 8 * LDA_ + 8);
            }
#pragma unroll
            for (int nt = 0; nt < 4; nt++) {
                const __half* base = Bc + (nWarp + nt * 8 + grp) * LDB_ + ks + 2 * qd;
                bf[nt][0] = *(const uint32_t*)(base);
                bf[nt][1] = *(const uint32_t*)(base + 8);
            }
#pragma unroll
            for (int mt = 0; mt < 4; mt++)
#pragma unroll
                for (int nt = 0; nt < 4; nt++)
                    mma_f16(acc[mt][nt], af[mt], bf[nt]);
        }
        __syncthreads();
    }

    // Epilogue
#pragma unroll
    for (int mt = 0; mt < 4; mt++) {
#pragma unroll
        for (int nt = 0; nt < 4; nt++) {
            const int row = mBase + mWarp + mt * 16 + grp;
            const int col = nBase + nWarp + nt * 8 + qd * 2;
            const float b0 = bias[col], b1 = bias[col + 1];
#pragma unroll
            for (int rr = 0; rr < 2; rr++) {
                const int r = row + rr * 8;
                const size_t base = (size_t)r * N + col;
                float v0 = acc[mt][nt][rr * 2 + 0] + b0;
                float v1 = acc[mt][nt][rr * 2 + 1] + b1;
                if (GELU) {
                    v0 = 0.5f * v0 * (1.0f + erff(v0 * 0.70710678118654752f));
                    v1 = 0.5f * v1 * (1.0f + erff(v1 * 0.70710678118654752f));
                }
                if (HASRES) {
                    float2 rv = *(const float2*)(res + base);
                    v0 += rv.x; v1 += rv.y;
                }
                if (OUTH) {
                    *(__half2*)(Ch + base) = __floats2half2_rn(v0, v1);
                } else {
                    float2 o; o.x = v0; o.y = v1;
                    *(float2*)(Cf + base) = o;
                }
            }
        }
    }
}

// ---------------------------------------------------------------------------
// Weight transpose + f32 -> half: out[c][r] = half(in[r][c]).
// ---------------------------------------------------------------------------
__global__ __launch_bounds__(256) void transposeh_kernel(
    const float* __restrict__ in, __half* __restrict__ out, int R, int C)
{
    __shared__ float t[32][33];
    const int cb = blockIdx.x * 32, rb = blockIdx.y * 32;
    const int tx = threadIdx.x & 31, ty = threadIdx.x >> 5;
#pragma unroll
    for (int j = 0; j < 4; j++)
        t[ty + j * 8][tx] = in[(size_t)(rb + ty + j * 8) * C + cb + tx];
    __syncthreads();
#pragma unroll
    for (int j = 0; j < 4; j++)
        out[(size_t)(cb + ty + j * 8) * R + rb + tx] = __float2half(t[tx][ty + j * 8]);
}

// f32 -> half elementwise (x pre-convert)
__global__ __launch_bounds__(256) void f2h_kernel(
    const float* __restrict__ in, __half* __restrict__ out, int n)
{
    const int i = (blockIdx.x * 256 + threadIdx.x) * 4;
    if (i < n) {
        float4 v = *(const float4*)(in + i);
        __half2 h0 = __floats2half2_rn(v.x, v.y);
        __half2 h1 = __floats2half2_rn(v.z, v.w);
        *(__half2*)(out + i)     = h0;
        *(__half2*)(out + i + 2) = h1;
    }
}

// ---------------------------------------------------------------------------
// FP16 tensor-core flash attention. qkv half [B*L][1536]. Out half [B*L][512].
// Block = (b,h,chunk,qtile): 4 warps x 32 q. Key tiles of 32. m16n8k16.
// ---------------------------------------------------------------------------
#define LDK_ 72
#define LDV_ 40
#define LDP_ 40

__device__ __forceinline__ float qmax4(float v) {
    v = fmaxf(v, __shfl_xor_sync(0xffffffffu, v, 1));
    v = fmaxf(v, __shfl_xor_sync(0xffffffffu, v, 2));
    return v;
}
__device__ __forceinline__ float qsum4(float v) {
    v += __shfl_xor_sync(0xffffffffu, v, 1);
    v += __shfl_xor_sync(0xffffffffu, v, 2);
    return v;
}

__global__ __launch_bounds__(128, 2) void attn_h_kernel(
    const __half* __restrict__ qkv, const int* __restrict__ mask,
    __half* __restrict__ out)
{
    __shared__ __half Ks[32 * LDK_];
    __shared__ __half Vs[64 * LDV_];
    __shared__ __half Ps[4][32 * LDP_];
    __shared__ float biasS[32];

    const int blk = blockIdx.x;
    const int qt  = blk & 3;
    const int c   = (blk >> 2) & 3;
    const int bh  = blk >> 4;
    const int b   = bh >> 3, h = bh & 7;
    const int tid = threadIdx.x, lane = tid & 31, wid = tid >> 5;
    const int grp = lane >> 2, qd = lane & 3;
    const int lq0 = c * SCHUNK + qt * 128 + wid * 32;

    // Q a-frags straight from gmem (unscaled; 0.125 folded into score path)
    uint32_t qa[2][4][4];
#pragma unroll
    for (int mt = 0; mt < 2; mt++)
#pragma unroll
        for (int ks = 0; ks < 4; ks++) {
            const __half* q0 = qkv + (size_t)(b * LSEQ + lq0 + mt * 16 + grp) * QKV3
                               + h * HDIM + ks * 16 + 2 * qd;
            qa[mt][ks][0] = *(const uint32_t*)(q0);
            qa[mt][ks][1] = *(const uint32_t*)(q0 + (size_t)8 * QKV3);
            qa[mt][ks][2] = *(const uint32_t*)(q0 + 8);
            qa[mt][ks][3] = *(const uint32_t*)(q0 + (size_t)8 * QKV3 + 8);
        }

    float O[2][8][4];
#pragma unroll
    for (int mt = 0; mt < 2; mt++)
#pragma unroll
        for (int nt = 0; nt < 8; nt++)
#pragma unroll
            for (int f = 0; f < 4; f++) O[mt][nt][f] = 0.f;
    float mrow[2][2] = {{-1e30f, -1e30f}, {-1e30f, -1e30f}};
    float lrow[2][2] = {{0.f, 0.f}, {0.f, 0.f}};

    int k0 = (c - 1) * SCHUNK; if (k0 < 0) k0 = 0;
    int k1 = (c + 2) * SCHUNK; if (k1 > LSEQ) k1 = LSEQ;

    __half* Pw = Ps[wid];

    for (int kt = k0; kt < k1; kt += 32) {
        __syncthreads();
        // Stage K [32 keys][64] and V transposed [64][32 keys]
        {
            const int key = tid >> 2;
            const int seg = (tid & 3) * 16;          // 16 halves per thread
            const __half* kp = qkv + (size_t)(b * LSEQ + kt + key) * QKV3
                               + DMODEL + h * HDIM + seg;
            *(float4*)(Ks + key * LDK_ + seg)     = *(const float4*)(kp);
            *(float4*)(Ks + key * LDK_ + seg + 8) = *(const float4*)(kp + 8);
            // V: same rows, +DMODEL; scatter transpose
            __half vt[16];
            *(float4*)(vt)     = *(const float4*)(kp + DMODEL);
            *(float4*)(vt + 8) = *(const float4*)(kp + DMODEL + 8);
#pragma unroll
            for (int j = 0; j < 16; j++)
                Vs[(seg + j) * LDV_ + key] = vt[j];
        }
        if (tid < 32) biasS[tid] = mask[b * LSEQ + kt + tid] ? -1e30f : 0.f;
        __syncthreads();

        // S = Q K^T (f32 accum), 32q x 32keys per warp
        float sc[2][4][4];
#pragma unroll
        for (int mt = 0; mt < 2; mt++)
#pragma unroll
            for (int nt = 0; nt < 4; nt++)
#pragma unroll
                for (int f = 0; f < 4; f++) sc[mt][nt][f] = 0.f;
#pragma unroll
        for (int ks = 0; ks < 4; ks++) {
            uint32_t kb[4][2];
#pragma unroll
            for (int nt = 0; nt < 4; nt++) {
                const __half* kbase = Ks + (nt * 8 + grp) * LDK_ + ks * 16 + 2 * qd;
                kb[nt][0] = *(const uint32_t*)(kbase);
                kb[nt][1] = *(const uint32_t*)(kbase + 8);
            }
#pragma unroll
            for (int mt = 0; mt < 2; mt++)
#pragma unroll
                for (int nt = 0; nt < 4; nt++)
                    mma_f16(sc[mt][nt], qa[mt][ks], kb[nt]);
        }

        // scale + mask
        float bs0[4], bs1[4];
#pragma unroll
        for (int nt = 0; nt < 4; nt++) {
            bs0[nt] = biasS[nt * 8 + 2 * qd];
            bs1[nt] = biasS[nt * 8 + 2 * qd + 1];
        }
#pragma unroll
        for (int mt = 0; mt < 2; mt++)
#pragma unroll
            for (int nt = 0; nt < 4; nt++) {
                sc[mt][nt][0] = sc[mt][nt][0] * 0.125f + bs0[nt];
                sc[mt][nt][1] = sc[mt][nt][1] * 0.125f + bs1[nt];
                sc[mt][nt][2] = sc[mt][nt][2] * 0.125f + bs0[nt];
                sc[mt][nt][3] = sc[mt][nt][3] * 0.125f + bs1[nt];
            }

        // Online softmax
        float scl[2][2];
#pragma unroll
        for (int mt = 0; mt < 2; mt++) {
            float nm0 = -1e30f, nm1 = -1e30f;
#pragma unroll
            for (int nt = 0; nt < 4; nt++) {
                nm0 = fmaxf(nm0, fmaxf(sc[mt][nt][0], sc[mt][nt][1]));
                nm1 = fmaxf(nm1, fmaxf(sc[mt][nt][2], sc[mt][nt][3]));
            }
            nm0 = qmax4(nm0); nm1 = qmax4(nm1);
            const float m0 = fmaxf(mrow[mt][0], nm0);
            const float m1 = fmaxf(mrow[mt][1], nm1);
            scl[mt][0] = __expf(mrow[mt][0] - m0);
            scl[mt][1] = __expf(mrow[mt][1] - m1);
            lrow[mt][0] *= scl[mt][0];
            lrow[mt][1] *= scl[mt][1];
            mrow[mt][0] = m0; mrow[mt][1] = m1;
        }
#pragma unroll
        for (int mt = 0; mt < 2; mt++)
#pragma unroll
            for (int nt = 0; nt < 8; nt++) {
                O[mt][nt][0] *= scl[mt][0];
                O[mt][nt][1] *= scl[mt][0];
                O[mt][nt][2] *= scl[mt][1];
                O[mt][nt][3] *= scl[mt][1];
            }
        float rs[2][2] = {{0.f, 0.f}, {0.f, 0.f}};
#pragma unroll
        for (int mt = 0; mt < 2; mt++)
#pragma unroll
            for (int nt = 0; nt < 4; nt++) {
                float p0 = __expf(sc[mt][nt][0] - mrow[mt][0]);
                float p1 = __expf(sc[mt][nt][1] - mrow[mt][0]);
                float p2 = __expf(sc[mt][nt][2] - mrow[mt][1]);
                float p3 = __expf(sc[mt][nt][3] - mrow[mt][1]);
                rs[mt][0] += p0 + p1;
                rs[mt][1] += p2 + p3;
                *(__half2*)&Pw[(mt * 16 + grp)     * LDP_ + nt * 8 + 2 * qd] = __floats2half2_rn(p0, p1);
                *(__half2*)&Pw[(mt * 16 + grp + 8) * LDP_ + nt * 8 + 2 * qd] = __floats2half2_rn(p2, p3);
            }
#pragma unroll
        for (int mt = 0; mt < 2; mt++) {
            lrow[mt][0] += qsum4(rs[mt][0]);
            lrow[mt][1] += qsum4(rs[mt][1]);
        }
        __syncwarp();

        // O += P V (k=32 keys -> 2 ksteps)
#pragma unroll
        for (int ks = 0; ks < 2; ks++) {
            uint32_t pa[2][4];
#pragma unroll
            for (int mt = 0; mt < 2; mt++) {
                const __half* base = Pw + (mt * 16 + grp) * LDP_ + ks * 16 + 2 * qd;
                pa[mt][0] = *(const uint32_t*)(base);
                pa[mt][1] = *(const uint32_t*)(base + 8 * LDP_);
                pa[mt][2] = *(const uint32_t*)(base + 8);
                pa[mt][3] = *(const uint32_t*)(base + 8 * LDP_ + 8);
            }
            uint32_t vb[8][2];
#pragma unroll
            for (int nt = 0; nt < 8; nt++) {
                const __half* vbase = Vs + (nt * 8 + grp) * LDV_ + ks * 16 + 2 * qd;
                vb[nt][0] = *(const uint32_t*)(vbase);
                vb[nt][1] = *(const uint32_t*)(vbase + 8);
            }
#pragma unroll
            for (int mt = 0; mt < 2; mt++)
#pragma unroll
                for (int nt = 0; nt < 8; nt++)
                    mma_f16(O[mt][nt], pa[mt], vb[nt]);
        }
        __syncwarp();
    }

    // Normalize + store half to merged [B,L,D]
#pragma unroll
    for (int mt = 0; mt < 2; mt++) {
        const float inv0 = 1.0f / lrow[mt][0];
        const float inv1 = 1.0f / lrow[mt][1];
#pragma unroll
        for (int nt = 0; nt < 8; nt++) {
            const int row = lq0 + mt * 16 + grp;
            const int col = h * HDIM + nt * 8 + 2 * qd;
            *(__half2*)(out + (size_t)(b * LSEQ + row) * DMODEL + col) =
                __floats2half2_rn(O[mt][nt][0] * inv0, O[mt][nt][1] * inv0);
            *(__half2*)(out + (size_t)(b * LSEQ + row + 8) * DMODEL + col) =
                __floats2half2_rn(O[mt][nt][2] * inv1, O[mt][nt][3] * inv1);
        }
    }
}

// ---------------------------------------------------------------------------
// LayerNorm over last dim (512). EMITH: also write half copy.
// ---------------------------------------------------------------------------
template<int EMITH>
__global__ __launch_bounds__(128) void ln_kernel(
    const float* __restrict__ in, const float* __restrict__ gg,
    const float* __restrict__ bb, float* __restrict__ out,
    __half* __restrict__ outh)
{
    const int row = blockIdx.x, tid = threadIdx.x;
    const float* p = in + (size_t)row * DMODEL;
    float4 v = *(const float4*)(p + tid * 4);
    float s  = v.x + v.y + v.z + v.w;
    float ss = v.x * v.x + v.y * v.y + v.z * v.z + v.w * v.w;
#pragma unroll
    for (int o = 16; o > 0; o >>= 1) {
        s  += __shfl_xor_sync(0xffffffffu, s,  o);
        ss += __shfl_xor_sync(0xffffffffu, ss, o);
    }
    __shared__ float sh[8];
    const int w = tid >> 5, ln = tid & 31;
    if (ln == 0) { sh[w] = s; sh[4 + w] = ss; }
    __syncthreads();
    s  = sh[0] + sh[1] + sh[2] + sh[3];
    ss = sh[4] + sh[5] + sh[6] + sh[7];
    const float mu  = s * (1.0f / DMODEL);
    const float var = ss * (1.0f / DMODEL) - mu * mu;
    const float inv = rsqrtf(var + 1e-5f);
    float4 gv = *(const float4*)(gg + tid * 4);
    float4 bv = *(const float4*)(bb + tid * 4);
    float4 o4;
    o4.x = (v.x - mu) * inv * gv.x + bv.x;
    o4.y = (v.y - mu) * inv * gv.y + bv.y;
    o4.z = (v.z - mu) * inv * gv.z + bv.z;
    o4.w = (v.w - mu) * inv * gv.w + bv.w;
    *(float4*)(out + (size_t)row * DMODEL + tid * 4) = o4;
    if (EMITH) {
        *(__half2*)(outh + (size_t)row * DMODEL + tid * 4)     = __floats2half2_rn(o4.x, o4.y);
        *(__half2*)(outh + (size_t)row * DMODEL + tid * 4 + 2) = __floats2half2_rn(o4.z, o4.w);
    }
}

// ---------------------------------------------------------------------------
extern "C" void kernel_launch(void* const* d_in, const int* in_sizes, int n_in,
                              void* d_out, int out_size)
{
    const float* x      = (const float*)d_in[0];
    const int*   mask   = (const int*)  d_in[1];
    const float* qkv_w  = (const float*)d_in[2];
    const float* qkv_b  = (const float*)d_in[3];
    const float* out_w  = (const float*)d_in[4];
    const float* out_b  = (const float*)d_in[5];
    const float* ffn_w1 = (const float*)d_in[6];
    const float* ffn_b1 = (const float*)d_in[7];
    const float* ffn_w2 = (const float*)d_in[8];
    const float* ffn_b2 = (const float*)d_in[9];
    const float* ln1_g  = (const float*)d_in[10];
    const float* ln1_b  = (const float*)d_in[11];
    const float* ln2_g  = (const float*)d_in[12];
    const float* ln2_b  = (const float*)d_in[13];
    float* out = (float*)d_out;

    __half *qkvh, *attnh, *ffnh, *xh, *x1h, *qkvwT, *outwT, *ffn1T, *ffn2T;
    float *x1p, *prep;
    cudaGetSymbolAddress((void**)&qkvh,  g_qkvh);
    cudaGetSymbolAddress((void**)&attnh, g_attnh);
    cudaGetSymbolAddress((void**)&ffnh,  g_ffnh);
    cudaGetSymbolAddress((void**)&xh,    g_xh);
    cudaGetSymbolAddress((void**)&x1h,   g_x1h);
    cudaGetSymbolAddress((void**)&x1p,   g_x1);
    cudaGetSymbolAddress((void**)&prep,  g_pre);
    cudaGetSymbolAddress((void**)&qkvwT, g_qkvwT);
    cudaGetSymbolAddress((void**)&outwT, g_outwT);
    cudaGetSymbolAddress((void**)&ffn1T, g_ffn1T);
    cudaGetSymbolAddress((void**)&ffn2T, g_ffn2T);

    // 0) Pre-convert x and weights (half, weights transposed to [N][K])
    f2h_kernel<<<(BL * DMODEL / 4 + 255) / 256, 256>>>(x, xh, BL * DMODEL);
    transposeh_kernel<<<dim3(QKV3 / 32, DMODEL / 32), 256>>>(qkv_w, qkvwT, DMODEL, QKV3);
    transposeh_kernel<<<dim3(DMODEL / 32, DMODEL / 32), 256>>>(out_w, outwT, DMODEL, DMODEL);
    transposeh_kernel<<<dim3(FFND / 32, DMODEL / 32), 256>>>(ffn_w1, ffn1T, DMODEL, FFND);
    transposeh_kernel<<<dim3(DMODEL / 32, FFND / 32), 256>>>(ffn_w2, ffn2T, FFND, DMODEL);

    // 1) QKV = X @ qkv_w + qkv_b  -> half
    hgemm_kernel<0,0,1><<<dim3(QKV3 / 128, BL / 128), 256>>>(
        xh, qkvwT, qkv_b, nullptr, qkvh, nullptr, BL, QKV3, DMODEL);

    // 2) Attention -> half merged [B,L,D]
    attn_h_kernel<<<512, 128>>>(qkvh, mask, attnh);

    // 3) pre1 = x + (attn @ out_w + out_b) -> f32
    hgemm_kernel<0,1,0><<<dim3(DMODEL / 128, BL / 128), 256>>>(
        attnh, outwT, out_b, x, nullptr, prep, BL, DMODEL, DMODEL);

    // 4) x1 = LN1(pre1) -> f32 + half
    ln_kernel<1><<<BL, 128>>>(prep, ln1_g, ln1_b, x1p, x1h);

    // 5) h = gelu(x1 @ ffn_w1 + ffn_b1) -> half
    hgemm_kernel<1,0,1><<<dim3(FFND / 128, BL / 128), 256>>>(
        x1h, ffn1T, ffn_b1, nullptr, ffnh, nullptr, BL, FFND, DMODEL);

    // 6) pre2 = x1 + (h @ ffn_w2 + ffn_b2) -> f32
    hgemm_kernel<0,1,0><<<dim3(DMODEL / 128, BL / 128), 256>>>(
        ffnh, ffn2T, ffn_b2, x1p, nullptr, prep, BL, DMODEL, FFND);

    // 7) out = LN2(pre2)
    ln_kernel<0><<<BL, 128>>>(prep, ln2_g, ln2_b, out, nullptr);
}

// round 8
// speedup vs baseline: 6.9958x; 1.1376x over previous
#include <cuda_runtime.h>
#include <cuda_fp16.h>
#include <math.h>
#include <stdint.h>
#include <string.h>

#define BQ      4
#define LSEQ    2048
#define DMODEL  512
#define NHEAD   8
#define HDIM    64
#define FFND    2048
#define BL      (BQ * LSEQ)
#define QKV3    (3 * DMODEL)
#define SCHUNK  512

// Scratch (static device globals)
__device__ __half g_qkvh [BL * QKV3];
__device__ __half g_attnh[BL * DMODEL];
__device__ __half g_ffnh [BL * FFND];
__device__ __half g_xh   [BL * DMODEL];
__device__ __half g_x1h  [BL * DMODEL];
__device__ float  g_x1   [BL * DMODEL];
__device__ float  g_pre  [BL * DMODEL];
__device__ __half g_qkvwT[QKV3 * DMODEL];
__device__ __half g_outwT[DMODEL * DMODEL];
__device__ __half g_ffn1T[FFND * DMODEL];
__device__ __half g_ffn2T[DMODEL * FFND];

// ---------------------------------------------------------------------------
__device__ __forceinline__ uint32_t h2u(__half2 h) {
    uint32_t u; memcpy(&u, &h, 4); return u;
}
__device__ __forceinline__ void mma_f16(float* d, const uint32_t* a, const uint32_t* b) {
    asm volatile(
        "mma.sync.aligned.m16n8k16.row.col.f32.f16.f16.f32 "
        "{%0,%1,%2,%3}, {%4,%5,%6,%7}, {%8,%9}, {%0,%1,%2,%3};"
        : "+f"(d[0]), "+f"(d[1]), "+f"(d[2]), "+f"(d[3])
        : "r"(a[0]), "r"(a[1]), "r"(a[2]), "r"(a[3]), "r"(b[0]), "r"(b[1]));
}
__device__ __forceinline__ uint32_t smaddr(const void* p) {
    uint32_t a;
    asm("{.reg .u64 t; cvta.to.shared.u64 t, %1; cvt.u32.u64 %0, t;}" : "=r"(a) : "l"(p));
    return a;
}
#define CP16(dst, src) asm volatile("cp.async.cg.shared.global [%0], [%1], 16;" :: "r"(dst), "l"(src))
#define CPCOMMIT()     asm volatile("cp.async.commit_group;")
#define CPWAIT(n)      asm volatile("cp.async.wait_group %0;" :: "n"(n))
#define LDSM_X4(r0,r1,r2,r3,a) \
    asm volatile("ldmatrix.sync.aligned.m8n8.x4.shared.b16 {%0,%1,%2,%3}, [%4];" \
        : "=r"(r0), "=r"(r1), "=r"(r2), "=r"(r3) : "r"(a))
#define LDSM_X4T(r0,r1,r2,r3,a) \
    asm volatile("ldmatrix.sync.aligned.m8n8.x4.trans.shared.b16 {%0,%1,%2,%3}, [%4];" \
        : "=r"(r0), "=r"(r1), "=r"(r2), "=r"(r3) : "r"(a))

// ---------------------------------------------------------------------------
// FP16 tensor GEMM with ldmatrix fragment loads.
// Block 128x128, BK=32, 256 thr = 8 warps (2M x 4N), warp 64x32, m16n8k16.
// Smem stride 40 halves (80B rows: 16B-aligned, LDSM conflict-free).
// ---------------------------------------------------------------------------
#define LDA_ 40
#define A_STAGE (128 * LDA_ * 2)   // bytes per stage

template<int GELU, int HASRES, int OUTH>
__global__ __launch_bounds__(256, 2) void hgemm_kernel(
    const __half* __restrict__ A, const __half* __restrict__ BT,
    const float* __restrict__ bias, const float* __restrict__ res,
    __half* __restrict__ Ch, float* __restrict__ Cf, int M, int N, int K)
{
    __shared__ __half As[2][128 * LDA_];
    __shared__ __half Bs[2][128 * LDA_];

    const int tid   = threadIdx.x;
    const int lane  = tid & 31, wid = tid >> 5;
    const int grp   = lane >> 2, qd = lane & 3;
    const int g     = lane >> 3, l7 = lane & 7;
    const int mBase = blockIdx.y * 128;
    const int nBase = blockIdx.x * 128;
    const int mWarp = (wid & 1) * 64;
    const int nWarp = (wid >> 1) * 32;

    // cp.async staging mapping
    const int sRow0 = tid >> 2,         sSeg0 = (tid & 3) * 8;
    const int sRow1 = (tid + 256) >> 2, sSeg1 = ((tid + 256) & 3) * 8;

    const __half* Ap0 = A  + (size_t)(mBase + sRow0) * K + sSeg0;
    const __half* Ap1 = A  + (size_t)(mBase + sRow1) * K + sSeg1;
    const __half* Bp0 = BT + (size_t)(nBase + sRow0) * K + sSeg0;
    const __half* Bp1 = BT + (size_t)(nBase + sRow1) * K + sSeg1;

    const uint32_t aBase = smaddr(As);
    const uint32_t bBase = smaddr(Bs);
    const uint32_t sA0 = aBase + (sRow0 * LDA_ + sSeg0) * 2;
    const uint32_t sA1 = aBase + (sRow1 * LDA_ + sSeg1) * 2;
    const uint32_t sB0 = bBase + (sRow0 * LDA_ + sSeg0) * 2;
    const uint32_t sB1 = bBase + (sRow1 * LDA_ + sSeg1) * 2;

    // ldmatrix lane geometry
    const int rowA = mWarp + (g & 1) * 8 + l7;   // + mt*16
    const int kA   = (g >> 1) * 8;               // + ks
    const int rowB = nWarp + (g >> 1) * 8 + l7;  // + nt*8
    const int kB   = (g & 1) * 8;                // + ks

    float acc[4][4][4];
#pragma unroll
    for (int mt = 0; mt < 4; mt++)
#pragma unroll
        for (int nt = 0; nt < 4; nt++)
#pragma unroll
            for (int f = 0; f < 4; f++) acc[mt][nt][f] = 0.f;

    const int niter = K >> 5;

    CP16(sA0, Ap0); CP16(sA1, Ap1);
    CP16(sB0, Bp0); CP16(sB1, Bp1);
    CPCOMMIT();

    for (int it = 0; it < niter; it++) {
        const int buf = it & 1;
        if (it + 1 < niter) {
            const int k0 = (it + 1) << 5;
            const uint32_t o = (buf ^ 1) * A_STAGE;
            CP16(sA0 + o, Ap0 + k0); CP16(sA1 + o, Ap1 + k0);
            CP16(sB0 + o, Bp0 + k0); CP16(sB1 + o, Bp1 + k0);
            CPCOMMIT();
            CPWAIT(1);
        } else {
            CPWAIT(0);
        }
        __syncthreads();

        const uint32_t aS = aBase + buf * A_STAGE;
        const uint32_t bS = bBase + buf * A_STAGE;
#pragma unroll
        for (int ks = 0; ks < 32; ks += 16) {
            uint32_t af[4][4], bf[4][2];
#pragma unroll
            for (int mt = 0; mt < 4; mt++)
                LDSM_X4(af[mt][0], af[mt][1], af[mt][2], af[mt][3],
                        aS + (((rowA + mt * 16) * LDA_) + ks + kA) * 2);
            LDSM_X4(bf[0][0], bf[0][1], bf[1][0], bf[1][1],
                    bS + ((rowB * LDA_) + ks + kB) * 2);
            LDSM_X4(bf[2][0], bf[2][1], bf[3][0], bf[3][1],
                    bS + (((rowB + 16) * LDA_) + ks + kB) * 2);
#pragma unroll
            for (int mt = 0; mt < 4; mt++)
#pragma unroll
                for (int nt = 0; nt < 4; nt++)
                    mma_f16(acc[mt][nt], af[mt], bf[nt]);
        }
        __syncthreads();
    }

    // Epilogue
#pragma unroll
    for (int mt = 0; mt < 4; mt++) {
#pragma unroll
        for (int nt = 0; nt < 4; nt++) {
            const int row = mBase + mWarp + mt * 16 + grp;
            const int col = nBase + nWarp + nt * 8 + qd * 2;
            const float b0 = bias[col], b1 = bias[col + 1];
#pragma unroll
            for (int rr = 0; rr < 2; rr++) {
                const int r = row + rr * 8;
                const size_t base = (size_t)r * N + col;
                float v0 = acc[mt][nt][rr * 2 + 0] + b0;
                float v1 = acc[mt][nt][rr * 2 + 1] + b1;
                if (GELU) {
                    v0 = 0.5f * v0 * (1.0f + erff(v0 * 0.70710678118654752f));
                    v1 = 0.5f * v1 * (1.0f + erff(v1 * 0.70710678118654752f));
                }
                if (HASRES) {
                    float2 rv = *(const float2*)(res + base);
                    v0 += rv.x; v1 += rv.y;
                }
                if (OUTH) {
                    *(__half2*)(Ch + base) = __floats2half2_rn(v0, v1);
                } else {
                    float2 o; o.x = v0; o.y = v1;
                    *(float2*)(Cf + base) = o;
                }
            }
        }
    }
}

// ---------------------------------------------------------------------------
// Merged prep: f2h of x (blocks 0..4095) + 4 weight transposes (f32->half,
// out[c][r] = in[r][c]) in one launch.
// ---------------------------------------------------------------------------
__global__ __launch_bounds__(256) void prep_kernel(
    const float* __restrict__ x,
    const float* __restrict__ qkv_w, const float* __restrict__ out_w,
    const float* __restrict__ ffn_w1, const float* __restrict__ ffn_w2,
    __half* __restrict__ xh, __half* __restrict__ qkvwT, __half* __restrict__ outwT,
    __half* __restrict__ ffn1T, __half* __restrict__ ffn2T)
{
    int bid = blockIdx.x;
    if (bid < 4096) {
        const int i = bid * 1024 + threadIdx.x * 4;
        float4 v = *(const float4*)(x + i);
        *(__half2*)(xh + i)     = __floats2half2_rn(v.x, v.y);
        *(__half2*)(xh + i + 2) = __floats2half2_rn(v.z, v.w);
        return;
    }
    bid -= 4096;
    const float* in; __half* outp; int C, t, R;
    if (bid < 768)       { in = qkv_w;  outp = qkvwT; R = DMODEL; C = QKV3;   t = bid; }
    else if (bid < 1024) { in = out_w;  outp = outwT; R = DMODEL; C = DMODEL; t = bid - 768; }
    else if (bid < 2048) { in = ffn_w1; outp = ffn1T; R = DMODEL; C = FFND;   t = bid - 1024; }
    else                 { in = ffn_w2; outp = ffn2T; R = FFND;   C = DMODEL; t = bid - 2048; }
    const int tilesC = C >> 5;
    const int cb = (t % tilesC) * 32, rb = (t / tilesC) * 32;

    __shared__ float tt[32][33];
    const int tx = threadIdx.x & 31, ty = threadIdx.x >> 5;
#pragma unroll
    for (int j = 0; j < 4; j++)
        tt[ty + j * 8][tx] = in[(size_t)(rb + ty + j * 8) * C + cb + tx];
    __syncthreads();
#pragma unroll
    for (int j = 0; j < 4; j++)
        outp[(size_t)(cb + ty + j * 8) * R + rb + tx] = __float2half(tt[tx][ty + j * 8]);
}

// ---------------------------------------------------------------------------
// FP16 flash attention, register-resident P, ldmatrix K/V frags, cp.async
// double-buffered K/V staging. Block = 4 warps x 32 q = 128 q rows.
// K,V smem row-major [32 keys][64 d], stride 72 halves (144B).
// Staging: 64 threads per tile, each owns a contiguous 64B half-row and
// issues 4 CP16s -> 64*4*16B = 4096B = full tile. (R7 bug: was 1 CP16.)
// ---------------------------------------------------------------------------
#define LDK_ 72
#define KV_STAGE (32 * LDK_ * 2)   // bytes per K (or V) stage

__device__ __forceinline__ float qmax4(float v) {
    v = fmaxf(v, __shfl_xor_sync(0xffffffffu, v, 1));
    v = fmaxf(v, __shfl_xor_sync(0xffffffffu, v, 2));
    return v;
}
__device__ __forceinline__ float qsum4(float v) {
    v += __shfl_xor_sync(0xffffffffu, v, 1);
    v += __shfl_xor_sync(0xffffffffu, v, 2);
    return v;
}

__global__ __launch_bounds__(128, 2) void attn_h_kernel(
    const __half* __restrict__ qkv, const int* __restrict__ mask,
    __half* __restrict__ out)
{
    __shared__ __half Ks[2][32 * LDK_];
    __shared__ __half Vs[2][32 * LDK_];
    __shared__ float biasS[2][32];

    const int blk = blockIdx.x;
    const int qt  = blk & 3;
    const int c   = (blk >> 2) & 3;
    const int bh  = blk >> 4;
    const int b   = bh >> 3, h = bh & 7;
    const int tid = threadIdx.x, lane = tid & 31, wid = tid >> 5;
    const int grp = lane >> 2, qd = lane & 3;
    const int g   = lane >> 3, l7 = lane & 7;
    const int lq0 = c * SCHUNK + qt * 128 + wid * 32;

    const uint32_t kBase = smaddr(Ks);
    const uint32_t vBase = smaddr(Vs);

    // ldmatrix lane geometry
    const int rowK = (g >> 1) * 8 + l7;   // + nt*8 (keys)
    const int kK   = (g & 1) * 8;         // + ks*16 (d)
    const int rowV = (g & 1) * 8 + l7;    // + ks*16 (keys)
    const int colV = (g >> 1) * 8;        // + ntp*8 (d)

    // cp.async staging: tid 0-63 -> K, 64-127 -> V; 32 rows x 2 half-rows,
    // 4 CP16 (64B) per thread.
    const int stRow = (tid & 63) >> 1;
    const int stSeg = (tid & 1) * 32;     // halves
    const int isV   = tid >> 6;
    const uint32_t stDst = (isV ? vBase : kBase) + (stRow * LDK_ + stSeg) * 2;
    const size_t   stSrcOff = (size_t)DMODEL + (size_t)isV * DMODEL + h * HDIM + stSeg;

    // Q a-frags from gmem
    uint32_t qa[2][4][4];
#pragma unroll
    for (int mt = 0; mt < 2; mt++)
#pragma unroll
        for (int ks = 0; ks < 4; ks++) {
            const __half* q0 = qkv + (size_t)(b * LSEQ + lq0 + mt * 16 + grp) * QKV3
                               + h * HDIM + ks * 16 + 2 * qd;
            qa[mt][ks][0] = *(const uint32_t*)(q0);
            qa[mt][ks][1] = *(const uint32_t*)(q0 + (size_t)8 * QKV3);
            qa[mt][ks][2] = *(const uint32_t*)(q0 + 8);
            qa[mt][ks][3] = *(const uint32_t*)(q0 + (size_t)8 * QKV3 + 8);
        }

    float O[2][8][4];
#pragma unroll
    for (int mt = 0; mt < 2; mt++)
#pragma unroll
        for (int nt = 0; nt < 8; nt++)
#pragma unroll
            for (int f = 0; f < 4; f++) O[mt][nt][f] = 0.f;
    float mrow[2][2] = {{-1e30f, -1e30f}, {-1e30f, -1e30f}};
    float lrow[2][2] = {{0.f, 0.f}, {0.f, 0.f}};

    int k0 = (c - 1) * SCHUNK; if (k0 < 0) k0 = 0;
    int k1 = (c + 2) * SCHUNK; if (k1 > LSEQ) k1 = LSEQ;
    const int niter = (k1 - k0) >> 5;

    // prologue: tile 0 -> buf 0
    {
        const __half* src = qkv + (size_t)(b * LSEQ + k0 + stRow) * QKV3 + stSrcOff;
        CP16(stDst,      src);
        CP16(stDst + 16, src + 8);
        CP16(stDst + 32, src + 16);
        CP16(stDst + 48, src + 24);
        if (tid < 32) biasS[0][tid] = mask[b * LSEQ + k0 + tid] ? -1e30f : 0.f;
        CPCOMMIT();
    }

    for (int it = 0; it < niter; it++) {
        const int buf = it & 1;
        if (it + 1 < niter) {
            const int ktn = k0 + (it + 1) * 32;
            const __half* src = qkv + (size_t)(b * LSEQ + ktn + stRow) * QKV3 + stSrcOff;
            const uint32_t d = stDst + (buf ^ 1) * KV_STAGE;
            CP16(d,      src);
            CP16(d + 16, src + 8);
            CP16(d + 32, src + 16);
            CP16(d + 48, src + 24);
            if (tid < 32) biasS[buf ^ 1][tid] = mask[b * LSEQ + ktn + tid] ? -1e30f : 0.f;
            CPCOMMIT();
            CPWAIT(1);
        } else {
            CPWAIT(0);
        }
        __syncthreads();

        const uint32_t kS = kBase + buf * KV_STAGE;
        const uint32_t vS = vBase + buf * KV_STAGE;

        // S = Q K^T
        float sc[2][4][4];
#pragma unroll
        for (int mt = 0; mt < 2; mt++)
#pragma unroll
            for (int nt = 0; nt < 4; nt++)
#pragma unroll
                for (int f = 0; f < 4; f++) sc[mt][nt][f] = 0.f;
#pragma unroll
        for (int ks = 0; ks < 4; ks++) {
            uint32_t kb[4][2];
            LDSM_X4(kb[0][0], kb[0][1], kb[1][0], kb[1][1],
                    kS + ((rowK * LDK_) + ks * 16 + kK) * 2);
            LDSM_X4(kb[2][0], kb[2][1], kb[3][0], kb[3][1],
                    kS + (((rowK + 16) * LDK_) + ks * 16 + kK) * 2);
#pragma unroll
            for (int mt = 0; mt < 2; mt++)
#pragma unroll
                for (int nt = 0; nt < 4; nt++)
                    mma_f16(sc[mt][nt], qa[mt][ks], kb[nt]);
        }

        // scale + mask
        float bs0[4], bs1[4];
#pragma unroll
        for (int nt = 0; nt < 4; nt++) {
            bs0[nt] = biasS[buf][nt * 8 + 2 * qd];
            bs1[nt] = biasS[buf][nt * 8 + 2 * qd + 1];
        }
#pragma unroll
        for (int mt = 0; mt < 2; mt++)
#pragma unroll
            for (int nt = 0; nt < 4; nt++) {
                sc[mt][nt][0] = sc[mt][nt][0] * 0.125f + bs0[nt];
                sc[mt][nt][1] = sc[mt][nt][1] * 0.125f + bs1[nt];
                sc[mt][nt][2] = sc[mt][nt][2] * 0.125f + bs0[nt];
                sc[mt][nt][3] = sc[mt][nt][3] * 0.125f + bs1[nt];
            }

        // Online softmax (c-layout; rows grp/grp+8, cols across qd lanes)
        float scl[2][2];
#pragma unroll
        for (int mt = 0; mt < 2; mt++) {
            float nm0 = -1e30f, nm1 = -1e30f;
#pragma unroll
            for (int nt = 0; nt < 4; nt++) {
                nm0 = fmaxf(nm0, fmaxf(sc[mt][nt][0], sc[mt][nt][1]));
                nm1 = fmaxf(nm1, fmaxf(sc[mt][nt][2], sc[mt][nt][3]));
            }
            nm0 = qmax4(nm0); nm1 = qmax4(nm1);
            const float m0 = fmaxf(mrow[mt][0], nm0);
            const float m1 = fmaxf(mrow[mt][1], nm1);
            scl[mt][0] = __expf(mrow[mt][0] - m0);
            scl[mt][1] = __expf(mrow[mt][1] - m1);
            lrow[mt][0] *= scl[mt][0];
            lrow[mt][1] *= scl[mt][1];
            mrow[mt][0] = m0; mrow[mt][1] = m1;
        }
#pragma unroll
        for (int mt = 0; mt < 2; mt++)
#pragma unroll
            for (int nt = 0; nt < 8; nt++) {
                O[mt][nt][0] *= scl[mt][0];
                O[mt][nt][1] *= scl[mt][0];
                O[mt][nt][2] *= scl[mt][1];
                O[mt][nt][3] *= scl[mt][1];
            }

        // exp -> register-resident P a-frags (c-layout == a-layout)
        uint32_t pf[2][2][4];
        float rs[2][2] = {{0.f, 0.f}, {0.f, 0.f}};
#pragma unroll
        for (int mt = 0; mt < 2; mt++)
#pragma unroll
            for (int nt = 0; nt < 4; nt++) {
                const float p0 = __expf(sc[mt][nt][0] - mrow[mt][0]);
                const float p1 = __expf(sc[mt][nt][1] - mrow[mt][0]);
                const float p2 = __expf(sc[mt][nt][2] - mrow[mt][1]);
                const float p3 = __expf(sc[mt][nt][3] - mrow[mt][1]);
                rs[mt][0] += p0 + p1;
                rs[mt][1] += p2 + p3;
                const int ks = nt >> 1, hf = nt & 1;   // col tile -> PV kstep
                pf[mt][ks][hf * 2 + 0] = h2u(__floats2half2_rn(p0, p1));  // a0 / a2
                pf[mt][ks][hf * 2 + 1] = h2u(__floats2half2_rn(p2, p3));  // a1 / a3
            }
#pragma unroll
        for (int mt = 0; mt < 2; mt++) {
            lrow[mt][0] += qsum4(rs[mt][0]);
            lrow[mt][1] += qsum4(rs[mt][1]);
        }

        // O += P V  (2 ksteps of 16 keys), V frags via ldmatrix.trans
#pragma unroll
        for (int ks = 0; ks < 2; ks++) {
            uint32_t vb[8][2];
#pragma unroll
            for (int ntp = 0; ntp < 8; ntp += 2)
                LDSM_X4T(vb[ntp][0], vb[ntp][1], vb[ntp + 1][0], vb[ntp + 1][1],
                         vS + (((ks * 16 + rowV) * LDK_) + ntp * 8 + colV) * 2);
#pragma unroll
            for (int mt = 0; mt < 2; mt++)
#pragma unroll
                for (int nt = 0; nt < 8; nt++)
                    mma_f16(O[mt][nt], pf[mt][ks], vb[nt]);
        }
        __syncthreads();
    }

    // Normalize + store half to merged [B,L,D]
#pragma unroll
    for (int mt = 0; mt < 2; mt++) {
        const float inv0 = 1.0f / lrow[mt][0];
        const float inv1 = 1.0f / lrow[mt][1];
#pragma unroll
        for (int nt = 0; nt < 8; nt++) {
            const int row = lq0 + mt * 16 + grp;
            const int col = h * HDIM + nt * 8 + 2 * qd;
            *(__half2*)(out + (size_t)(b * LSEQ + row) * DMODEL + col) =
                __floats2half2_rn(O[mt][nt][0] * inv0, O[mt][nt][1] * inv0);
            *(__half2*)(out + (size_t)(b * LSEQ + row + 8) * DMODEL + col) =
                __floats2half2_rn(O[mt][nt][2] * inv1, O[mt][nt][3] * inv1);
        }
    }
}

// ---------------------------------------------------------------------------
template<int EMITH>
__global__ __launch_bounds__(128) void ln_kernel(
    const float* __restrict__ in, const float* __restrict__ gg,
    const float* __restrict__ bb, float* __restrict__ out,
    __half* __restrict__ outh)
{
    const int row = blockIdx.x, tid = threadIdx.x;
    const float* p = in + (size_t)row * DMODEL;
    float4 v = *(const float4*)(p + tid * 4);
    float s  = v.x + v.y + v.z + v.w;
    float ss = v.x * v.x + v.y * v.y + v.z * v.z + v.w * v.w;
#pragma unroll
    for (int o = 16; o > 0; o >>= 1) {
        s  += __shfl_xor_sync(0xffffffffu, s,  o);
        ss += __shfl_xor_sync(0xffffffffu, ss, o);
    }
    __shared__ float sh[8];
    const int w = tid >> 5, ln = tid & 31;
    if (ln == 0) { sh[w] = s; sh[4 + w] = ss; }
    __syncthreads();
    s  = sh[0] + sh[1] + sh[2] + sh[3];
    ss = sh[4] + sh[5] + sh[6] + sh[7];
    const float mu  = s * (1.0f / DMODEL);
    const float var = ss * (1.0f / DMODEL) - mu * mu;
    const float inv = rsqrtf(var + 1e-5f);
    float4 gv = *(const float4*)(gg + tid * 4);
    float4 bv = *(const float4*)(bb + tid * 4);
    float4 o4;
    o4.x = (v.x - mu) * inv * gv.x + bv.x;
    o4.y = (v.y - mu) * inv * gv.y + bv.y;
    o4.z = (v.z - mu) * inv * gv.z + bv.z;
    o4.w = (v.w - mu) * inv * gv.w + bv.w;
    *(float4*)(out + (size_t)row * DMODEL + tid * 4) = o4;
    if (EMITH) {
        *(__half2*)(outh + (size_t)row * DMODEL + tid * 4)     = __floats2half2_rn(o4.x, o4.y);
        *(__half2*)(outh + (size_t)row * DMODEL + tid * 4 + 2) = __floats2half2_rn(o4.z, o4.w);
    }
}

// ---------------------------------------------------------------------------
extern "C" void kernel_launch(void* const* d_in, const int* in_sizes, int n_in,
                              void* d_out, int out_size)
{
    const float* x      = (const float*)d_in[0];
    const int*   mask   = (const int*)  d_in[1];
    const float* qkv_w  = (const float*)d_in[2];
    const float* qkv_b  = (const float*)d_in[3];
    const float* out_w  = (const float*)d_in[4];
    const float* out_b  = (const float*)d_in[5];
    const float* ffn_w1 = (const float*)d_in[6];
    const float* ffn_b1 = (const float*)d_in[7];
    const float* ffn_w2 = (const float*)d_in[8];
    const float* ffn_b2 = (const float*)d_in[9];
    const float* ln1_g  = (const float*)d_in[10];
    const float* ln1_b  = (const float*)d_in[11];
    const float* ln2_g  = (const float*)d_in[12];
    const float* ln2_b  = (const float*)d_in[13];
    float* out = (float*)d_out;

    __half *qkvh, *attnh, *ffnh, *xh, *x1h, *qkvwT, *outwT, *ffn1T, *ffn2T;
    float *x1p, *prep;
    cudaGetSymbolAddress((void**)&qkvh,  g_qkvh);
    cudaGetSymbolAddress((void**)&attnh, g_attnh);
    cudaGetSymbolAddress((void**)&ffnh,  g_ffnh);
    cudaGetSymbolAddress((void**)&xh,    g_xh);
    cudaGetSymbolAddress((void**)&x1h,   g_x1h);
    cudaGetSymbolAddress((void**)&x1p,   g_x1);
    cudaGetSymbolAddress((void**)&prep,  g_pre);
    cudaGetSymbolAddress((void**)&qkvwT, g_qkvwT);
    cudaGetSymbolAddress((void**)&outwT, g_outwT);
    cudaGetSymbolAddress((void**)&ffn1T, g_ffn1T);
    cudaGetSymbolAddress((void**)&ffn2T, g_ffn2T);

    // 0) One merged prep launch: x->half + 4 weight transposes
    prep_kernel<<<7168, 256>>>(x, qkv_w, out_w, ffn_w1, ffn_w2,
                               xh, qkvwT, outwT, ffn1T, ffn2T);

    // 1) QKV = X @ qkv_w + qkv_b  -> half
    hgemm_kernel<0,0,1><<<dim3(QKV3 / 128, BL / 128), 256>>>(
        xh, qkvwT, qkv_b, nullptr, qkvh, nullptr, BL, QKV3, DMODEL);

    // 2) Attention -> half merged [B,L,D]
    attn_h_kernel<<<512, 128>>>(qkvh, mask, attnh);

    // 3) pre1 = x + (attn @ out_w + out_b) -> f32
    hgemm_kernel<0,1,0><<<dim3(DMODEL / 128, BL / 128), 256>>>(
        attnh, outwT, out_b, x, nullptr, prep, BL, DMODEL, DMODEL);

    // 4) x1 = LN1(pre1) -> f32 + half
    ln_kernel<1><<<BL, 128>>>(prep, ln1_g, ln1_b, x1p, x1h);

    // 5) h = gelu(x1 @ ffn_w1 + ffn_b1) -> half
    hgemm_kernel<1,0,1><<<dim3(FFND / 128, BL / 128), 256>>>(
        x1h, ffn1T, ffn_b1, nullptr, ffnh, nullptr, BL, FFND, DMODEL);

    // 6) pre2 = x1 + (h @ ffn_w2 + ffn_b2) -> f32
    hgemm_kernel<0,1,0><<<dim3(DMODEL / 128, BL / 128), 256>>>(
        ffnh, ffn2T, ffn_b2, x1p, nullptr, prep, BL, DMODEL, FFND);

    // 7) out = LN2(pre2)
    ln_kernel<0><<<BL, 128>>>(prep, ln2_g, ln2_b, out, nullptr);
}

// round 9
// speedup vs baseline: 7.3108x; 1.0450x over previous
#include <cuda_runtime.h>
#include <cuda_fp16.h>
#include <math.h>
#include <stdint.h>
#include <string.h>

#define BQ      4
#define LSEQ    2048
#define DMODEL  512
#define NHEAD   8
#define HDIM    64
#define FFND    2048
#define BL      (BQ * LSEQ)
#define QKV3    (3 * DMODEL)
#define SCHUNK  512

// Scratch (static device globals)
__device__ __half g_qkvh [BL * QKV3];
__device__ __half g_attnh[BL * DMODEL];
__device__ __half g_ffnh [BL * FFND];
__device__ __half g_xh   [BL * DMODEL];
__device__ __half g_x1h  [BL * DMODEL];
__device__ float  g_x1   [BL * DMODEL];
__device__ float  g_pre  [BL * DMODEL];
__device__ __half g_qkvwT[QKV3 * DMODEL];
__device__ __half g_outwT[DMODEL * DMODEL];
__device__ __half g_ffn1T[FFND * DMODEL];
__device__ __half g_ffn2T[DMODEL * FFND];

// ---------------------------------------------------------------------------
__device__ __forceinline__ uint32_t h2u(__half2 h) {
    uint32_t u; memcpy(&u, &h, 4); return u;
}
__device__ __forceinline__ void mma_f16(float* d, const uint32_t* a, const uint32_t* b) {
    asm volatile(
        "mma.sync.aligned.m16n8k16.row.col.f32.f16.f16.f32 "
        "{%0,%1,%2,%3}, {%4,%5,%6,%7}, {%8,%9}, {%0,%1,%2,%3};"
        : "+f"(d[0]), "+f"(d[1]), "+f"(d[2]), "+f"(d[3])
        : "r"(a[0]), "r"(a[1]), "r"(a[2]), "r"(a[3]), "r"(b[0]), "r"(b[1]));
}
__device__ __forceinline__ uint32_t smaddr(const void* p) {
    uint32_t a;
    asm("{.reg .u64 t; cvta.to.shared.u64 t, %1; cvt.u32.u64 %0, t;}" : "=r"(a) : "l"(p));
    return a;
}
#define CP16(dst, src) asm volatile("cp.async.cg.shared.global [%0], [%1], 16;" :: "r"(dst), "l"(src))
#define CPCOMMIT()     asm volatile("cp.async.commit_group;")
#define CPWAIT(n)      asm volatile("cp.async.wait_group %0;" :: "n"(n))
#define LDSM_X4(r0,r1,r2,r3,a) \
    asm volatile("ldmatrix.sync.aligned.m8n8.x4.shared.b16 {%0,%1,%2,%3}, [%4];" \
        : "=r"(r0), "=r"(r1), "=r"(r2), "=r"(r3) : "r"(a))
#define LDSM_X4T(r0,r1,r2,r3,a) \
    asm volatile("ldmatrix.sync.aligned.m8n8.x4.trans.shared.b16 {%0,%1,%2,%3}, [%4];" \
        : "=r"(r0), "=r"(r1), "=r"(r2), "=r"(r3) : "r"(a))

// ---------------------------------------------------------------------------
// FP16 tensor GEMM, 4-stage cp.async pipeline, ldmatrix frags.
// Block 128x128, BK=32, 256 thr = 8 warps (2M x 4N), warp 64x32, m16n8k16.
// Dynamic smem: 4 stages x (A 10240B + B 10240B) = 81920B.
// One __syncthreads per K-iter; empty commit groups keep CPWAIT(2) valid.
// ---------------------------------------------------------------------------
#define LDA_ 40
#define A_STAGE (128 * LDA_ * 2)       // 10240 bytes per stage per operand
#define NSTAGE  4
#define GSMEM   (2 * NSTAGE * A_STAGE) // 81920

template<int GELU, int HASRES, int OUTH>
__global__ __launch_bounds__(256, 2) void hgemm_kernel(
    const __half* __restrict__ A, const __half* __restrict__ BT,
    const float* __restrict__ bias, const float* __restrict__ res,
    __half* __restrict__ Ch, float* __restrict__ Cf, int M, int N, int K)
{
    extern __shared__ __half smem_dyn[];

    const int tid   = threadIdx.x;
    const int lane  = tid & 31, wid = tid >> 5;
    const int grp   = lane >> 2, qd = lane & 3;
    const int g     = lane >> 3, l7 = lane & 7;
    const int mBase = blockIdx.y * 128;
    const int nBase = blockIdx.x * 128;
    const int mWarp = (wid & 1) * 64;
    const int nWarp = (wid >> 1) * 32;

    // cp.async staging mapping (full 128x32 tile per operand per stage)
    const int sRow0 = tid >> 2,         sSeg0 = (tid & 3) * 8;
    const int sRow1 = (tid + 256) >> 2, sSeg1 = ((tid + 256) & 3) * 8;

    const __half* Ap0 = A  + (size_t)(mBase + sRow0) * K + sSeg0;
    const __half* Ap1 = A  + (size_t)(mBase + sRow1) * K + sSeg1;
    const __half* Bp0 = BT + (size_t)(nBase + sRow0) * K + sSeg0;
    const __half* Bp1 = BT + (size_t)(nBase + sRow1) * K + sSeg1;

    const uint32_t aBase = smaddr(smem_dyn);
    const uint32_t bBase = aBase + NSTAGE * A_STAGE;
    const uint32_t sA0 = aBase + (sRow0 * LDA_ + sSeg0) * 2;
    const uint32_t sA1 = aBase + (sRow1 * LDA_ + sSeg1) * 2;
    const uint32_t sB0 = bBase + (sRow0 * LDA_ + sSeg0) * 2;
    const uint32_t sB1 = bBase + (sRow1 * LDA_ + sSeg1) * 2;

    // ldmatrix lane geometry
    const int rowA = mWarp + (g & 1) * 8 + l7;
    const int kA   = (g >> 1) * 8;
    const int rowB = nWarp + (g >> 1) * 8 + l7;
    const int kB   = (g & 1) * 8;

    float acc[4][4][4];
#pragma unroll
    for (int mt = 0; mt < 4; mt++)
#pragma unroll
        for (int nt = 0; nt < 4; nt++)
#pragma unroll
            for (int f = 0; f < 4; f++) acc[mt][nt][f] = 0.f;

    const int niter = K >> 5;

    // prologue: issue stages 0..2
#pragma unroll
    for (int s = 0; s < NSTAGE - 1; s++) {
        const int k0 = s << 5;
        const uint32_t o = s * A_STAGE;
        CP16(sA0 + o, Ap0 + k0); CP16(sA1 + o, Ap1 + k0);
        CP16(sB0 + o, Bp0 + k0); CP16(sB1 + o, Bp1 + k0);
        CPCOMMIT();
    }

    for (int it = 0; it < niter; it++) {
        CPWAIT(NSTAGE - 2);
        __syncthreads();

        // issue tile it+3 into slot (it+3)%4 == (it-1)%4 (consumed last iter)
        if (it + NSTAGE - 1 < niter) {
            const int k0 = (it + NSTAGE - 1) << 5;
            const uint32_t o = ((it + NSTAGE - 1) & (NSTAGE - 1)) * A_STAGE;
            CP16(sA0 + o, Ap0 + k0); CP16(sA1 + o, Ap1 + k0);
            CP16(sB0 + o, Bp0 + k0); CP16(sB1 + o, Bp1 + k0);
        }
        CPCOMMIT();   // empty group when exhausted: keeps group-count invariant

        const uint32_t aS = aBase + (it & (NSTAGE - 1)) * A_STAGE;
        const uint32_t bS = bBase + (it & (NSTAGE - 1)) * A_STAGE;
#pragma unroll
        for (int ks = 0; ks < 32; ks += 16) {
            uint32_t af[4][4], bf[4][2];
#pragma unroll
            for (int mt = 0; mt < 4; mt++)
                LDSM_X4(af[mt][0], af[mt][1], af[mt][2], af[mt][3],
                        aS + (((rowA + mt * 16) * LDA_) + ks + kA) * 2);
            LDSM_X4(bf[0][0], bf[0][1], bf[1][0], bf[1][1],
                    bS + ((rowB * LDA_) + ks + kB) * 2);
            LDSM_X4(bf[2][0], bf[2][1], bf[3][0], bf[3][1],
                    bS + (((rowB + 16) * LDA_) + ks + kB) * 2);
#pragma unroll
            for (int mt = 0; mt < 4; mt++)
#pragma unroll
                for (int nt = 0; nt < 4; nt++)
                    mma_f16(acc[mt][nt], af[mt], bf[nt]);
        }
    }

    // Epilogue
#pragma unroll
    for (int mt = 0; mt < 4; mt++) {
#pragma unroll
        for (int nt = 0; nt < 4; nt++) {
            const int row = mBase + mWarp + mt * 16 + grp;
            const int col = nBase + nWarp + nt * 8 + qd * 2;
            const float b0 = bias[col], b1 = bias[col + 1];
#pragma unroll
            for (int rr = 0; rr < 2; rr++) {
                const int r = row + rr * 8;
                const size_t base = (size_t)r * N + col;
                float v0 = acc[mt][nt][rr * 2 + 0] + b0;
                float v1 = acc[mt][nt][rr * 2 + 1] + b1;
                if (GELU) {
                    v0 = 0.5f * v0 * (1.0f + erff(v0 * 0.70710678118654752f));
                    v1 = 0.5f * v1 * (1.0f + erff(v1 * 0.70710678118654752f));
                }
                if (HASRES) {
                    float2 rv = *(const float2*)(res + base);
                    v0 += rv.x; v1 += rv.y;
                }
                if (OUTH) {
                    *(__half2*)(Ch + base) = __floats2half2_rn(v0, v1);
                } else {
                    float2 o; o.x = v0; o.y = v1;
                    *(float2*)(Cf + base) = o;
                }
            }
        }
    }
}

// ---------------------------------------------------------------------------
// Merged prep: f2h of x + 4 weight transposes in one launch.
// ---------------------------------------------------------------------------
__global__ __launch_bounds__(256) void prep_kernel(
    const float* __restrict__ x,
    const float* __restrict__ qkv_w, const float* __restrict__ out_w,
    const float* __restrict__ ffn_w1, const float* __restrict__ ffn_w2,
    __half* __restrict__ xh, __half* __restrict__ qkvwT, __half* __restrict__ outwT,
    __half* __restrict__ ffn1T, __half* __restrict__ ffn2T)
{
    int bid = blockIdx.x;
    if (bid < 4096) {
        const int i = bid * 1024 + threadIdx.x * 4;
        float4 v = *(const float4*)(x + i);
        *(__half2*)(xh + i)     = __floats2half2_rn(v.x, v.y);
        *(__half2*)(xh + i + 2) = __floats2half2_rn(v.z, v.w);
        return;
    }
    bid -= 4096;
    const float* in; __half* outp; int C, t, R;
    if (bid < 768)       { in = qkv_w;  outp = qkvwT; R = DMODEL; C = QKV3;   t = bid; }
    else if (bid < 1024) { in = out_w;  outp = outwT; R = DMODEL; C = DMODEL; t = bid - 768; }
    else if (bid < 2048) { in = ffn_w1; outp = ffn1T; R = DMODEL; C = FFND;   t = bid - 1024; }
    else                 { in = ffn_w2; outp = ffn2T; R = FFND;   C = DMODEL; t = bid - 2048; }
    const int tilesC = C >> 5;
    const int cb = (t % tilesC) * 32, rb = (t / tilesC) * 32;

    __shared__ float tt[32][33];
    const int tx = threadIdx.x & 31, ty = threadIdx.x >> 5;
#pragma unroll
    for (int j = 0; j < 4; j++)
        tt[ty + j * 8][tx] = in[(size_t)(rb + ty + j * 8) * C + cb + tx];
    __syncthreads();
#pragma unroll
    for (int j = 0; j < 4; j++)
        outp[(size_t)(cb + ty + j * 8) * R + rb + tx] = __float2half(tt[tx][ty + j * 8]);
}

// ---------------------------------------------------------------------------
// FP16 flash attention (register P, ldmatrix, cp.async 2-stage) — as R8.
// ---------------------------------------------------------------------------
#define LDK_ 72
#define KV_STAGE (32 * LDK_ * 2)

__device__ __forceinline__ float qmax4(float v) {
    v = fmaxf(v, __shfl_xor_sync(0xffffffffu, v, 1));
    v = fmaxf(v, __shfl_xor_sync(0xffffffffu, v, 2));
    return v;
}
__device__ __forceinline__ float qsum4(float v) {
    v += __shfl_xor_sync(0xffffffffu, v, 1);
    v += __shfl_xor_sync(0xffffffffu, v, 2);
    return v;
}

__global__ __launch_bounds__(128, 2) void attn_h_kernel(
    const __half* __restrict__ qkv, const int* __restrict__ mask,
    __half* __restrict__ out)
{
    __shared__ __half Ks[2][32 * LDK_];
    __shared__ __half Vs[2][32 * LDK_];
    __shared__ float biasS[2][32];

    const int blk = blockIdx.x;
    const int qt  = blk & 3;
    const int c   = (blk >> 2) & 3;
    const int bh  = blk >> 4;
    const int b   = bh >> 3, h = bh & 7;
    const int tid = threadIdx.x, lane = tid & 31, wid = tid >> 5;
    const int grp = lane >> 2, qd = lane & 3;
    const int g   = lane >> 3, l7 = lane & 7;
    const int lq0 = c * SCHUNK + qt * 128 + wid * 32;

    const uint32_t kBase = smaddr(Ks);
    const uint32_t vBase = smaddr(Vs);

    const int rowK = (g >> 1) * 8 + l7;
    const int kK   = (g & 1) * 8;
    const int rowV = (g & 1) * 8 + l7;
    const int colV = (g >> 1) * 8;

    const int stRow = (tid & 63) >> 1;
    const int stSeg = (tid & 1) * 32;
    const int isV   = tid >> 6;
    const uint32_t stDst = (isV ? vBase : kBase) + (stRow * LDK_ + stSeg) * 2;
    const size_t   stSrcOff = (size_t)DMODEL + (size_t)isV * DMODEL + h * HDIM + stSeg;

    uint32_t qa[2][4][4];
#pragma unroll
    for (int mt = 0; mt < 2; mt++)
#pragma unroll
        for (int ks = 0; ks < 4; ks++) {
            const __half* q0 = qkv + (size_t)(b * LSEQ + lq0 + mt * 16 + grp) * QKV3
                               + h * HDIM + ks * 16 + 2 * qd;
            qa[mt][ks][0] = *(const uint32_t*)(q0);
            qa[mt][ks][1] = *(const uint32_t*)(q0 + (size_t)8 * QKV3);
            qa[mt][ks][2] = *(const uint32_t*)(q0 + 8);
            qa[mt][ks][3] = *(const uint32_t*)(q0 + (size_t)8 * QKV3 + 8);
        }

    float O[2][8][4];
#pragma unroll
    for (int mt = 0; mt < 2; mt++)
#pragma unroll
        for (int nt = 0; nt < 8; nt++)
#pragma unroll
            for (int f = 0; f < 4; f++) O[mt][nt][f] = 0.f;
    float mrow[2][2] = {{-1e30f, -1e30f}, {-1e30f, -1e30f}};
    float lrow[2][2] = {{0.f, 0.f}, {0.f, 0.f}};

    int k0 = (c - 1) * SCHUNK; if (k0 < 0) k0 = 0;
    int k1 = (c + 2) * SCHUNK; if (k1 > LSEQ) k1 = LSEQ;
    const int niter = (k1 - k0) >> 5;

    {
        const __half* src = qkv + (size_t)(b * LSEQ + k0 + stRow) * QKV3 + stSrcOff;
        CP16(stDst,      src);
        CP16(stDst + 16, src + 8);
        CP16(stDst + 32, src + 16);
        CP16(stDst + 48, src + 24);
        if (tid < 32) biasS[0][tid] = mask[b * LSEQ + k0 + tid] ? -1e30f : 0.f;
        CPCOMMIT();
    }

    for (int it = 0; it < niter; it++) {
        const int buf = it & 1;
        if (it + 1 < niter) {
            const int ktn = k0 + (it + 1) * 32;
            const __half* src = qkv + (size_t)(b * LSEQ + ktn + stRow) * QKV3 + stSrcOff;
            const uint32_t d = stDst + (buf ^ 1) * KV_STAGE;
            CP16(d,      src);
            CP16(d + 16, src + 8);
            CP16(d + 32, src + 16);
            CP16(d + 48, src + 24);
            if (tid < 32) biasS[buf ^ 1][tid] = mask[b * LSEQ + ktn + tid] ? -1e30f : 0.f;
            CPCOMMIT();
            CPWAIT(1);
        } else {
            CPWAIT(0);
        }
        __syncthreads();

        const uint32_t kS = kBase + buf * KV_STAGE;
        const uint32_t vS = vBase + buf * KV_STAGE;

        float sc[2][4][4];
#pragma unroll
        for (int mt = 0; mt < 2; mt++)
#pragma unroll
            for (int nt = 0; nt < 4; nt++)
#pragma unroll
                for (int f = 0; f < 4; f++) sc[mt][nt][f] = 0.f;
#pragma unroll
        for (int ks = 0; ks < 4; ks++) {
            uint32_t kb[4][2];
            LDSM_X4(kb[0][0], kb[0][1], kb[1][0], kb[1][1],
                    kS + ((rowK * LDK_) + ks * 16 + kK) * 2);
            LDSM_X4(kb[2][0], kb[2][1], kb[3][0], kb[3][1],
                    kS + (((rowK + 16) * LDK_) + ks * 16 + kK) * 2);
#pragma unroll
            for (int mt = 0; mt < 2; mt++)
#pragma unroll
                for (int nt = 0; nt < 4; nt++)
                    mma_f16(sc[mt][nt], qa[mt][ks], kb[nt]);
        }

        float bs0[4], bs1[4];
#pragma unroll
        for (int nt = 0; nt < 4; nt++) {
            bs0[nt] = biasS[buf][nt * 8 + 2 * qd];
            bs1[nt] = biasS[buf][nt * 8 + 2 * qd + 1];
        }
#pragma unroll
        for (int mt = 0; mt < 2; mt++)
#pragma unroll
            for (int nt = 0; nt < 4; nt++) {
                sc[mt][nt][0] = sc[mt][nt][0] * 0.125f + bs0[nt];
                sc[mt][nt][1] = sc[mt][nt][1] * 0.125f + bs1[nt];
                sc[mt][nt][2] = sc[mt][nt][2] * 0.125f + bs0[nt];
                sc[mt][nt][3] = sc[mt][nt][3] * 0.125f + bs1[nt];
            }

        float scl[2][2];
#pragma unroll
        for (int mt = 0; mt < 2; mt++) {
            float nm0 = -1e30f, nm1 = -1e30f;
#pragma unroll
            for (int nt = 0; nt < 4; nt++) {
                nm0 = fmaxf(nm0, fmaxf(sc[mt][nt][0], sc[mt][nt][1]));
                nm1 = fmaxf(nm1, fmaxf(sc[mt][nt][2], sc[mt][nt][3]));
            }
            nm0 = qmax4(nm0); nm1 = qmax4(nm1);
            const float m0 = fmaxf(mrow[mt][0], nm0);
            const float m1 = fmaxf(mrow[mt][1], nm1);
            scl[mt][0] = __expf(mrow[mt][0] - m0);
            scl[mt][1] = __expf(mrow[mt][1] - m1);
            lrow[mt][0] *= scl[mt][0];
            lrow[mt][1] *= scl[mt][1];
            mrow[mt][0] = m0; mrow[mt][1] = m1;
        }
#pragma unroll
        for (int mt = 0; mt < 2; mt++)
#pragma unroll
            for (int nt = 0; nt < 8; nt++) {
                O[mt][nt][0] *= scl[mt][0];
                O[mt][nt][1] *= scl[mt][0];
                O[mt][nt][2] *= scl[mt][1];
                O[mt][nt][3] *= scl[mt][1];
            }

        uint32_t pf[2][2][4];
        float rs[2][2] = {{0.f, 0.f}, {0.f, 0.f}};
#pragma unroll
        for (int mt = 0; mt < 2; mt++)
#pragma unroll
            for (int nt = 0; nt < 4; nt++) {
                const float p0 = __expf(sc[mt][nt][0] - mrow[mt][0]);
                const float p1 = __expf(sc[mt][nt][1] - mrow[mt][0]);
                const float p2 = __expf(sc[mt][nt][2] - mrow[mt][1]);
                const float p3 = __expf(sc[mt][nt][3] - mrow[mt][1]);
                rs[mt][0] += p0 + p1;
                rs[mt][1] += p2 + p3;
                const int ks = nt >> 1, hf = nt & 1;
                pf[mt][ks][hf * 2 + 0] = h2u(__floats2half2_rn(p0, p1));
                pf[mt][ks][hf * 2 + 1] = h2u(__floats2half2_rn(p2, p3));
            }
#pragma unroll
        for (int mt = 0; mt < 2; mt++) {
            lrow[mt][0] += qsum4(rs[mt][0]);
            lrow[mt][1] += qsum4(rs[mt][1]);
        }

#pragma unroll
        for (int ks = 0; ks < 2; ks++) {
            uint32_t vb[8][2];
#pragma unroll
            for (int ntp = 0; ntp < 8; ntp += 2)
                LDSM_X4T(vb[ntp][0], vb[ntp][1], vb[ntp + 1][0], vb[ntp + 1][1],
                         vS + (((ks * 16 + rowV) * LDK_) + ntp * 8 + colV) * 2);
#pragma unroll
            for (int mt = 0; mt < 2; mt++)
#pragma unroll
                for (int nt = 0; nt < 8; nt++)
                    mma_f16(O[mt][nt], pf[mt][ks], vb[nt]);
        }
        __syncthreads();
    }

#pragma unroll
    for (int mt = 0; mt < 2; mt++) {
        const float inv0 = 1.0f / lrow[mt][0];
        const float inv1 = 1.0f / lrow[mt][1];
#pragma unroll
        for (int nt = 0; nt < 8; nt++) {
            const int row = lq0 + mt * 16 + grp;
            const int col = h * HDIM + nt * 8 + 2 * qd;
            *(__half2*)(out + (size_t)(b * LSEQ + row) * DMODEL + col) =
                __floats2half2_rn(O[mt][nt][0] * inv0, O[mt][nt][1] * inv0);
            *(__half2*)(out + (size_t)(b * LSEQ + row + 8) * DMODEL + col) =
                __floats2half2_rn(O[mt][nt][2] * inv1, O[mt][nt][3] * inv1);
        }
    }
}

// ---------------------------------------------------------------------------
template<int EMITH>
__global__ __launch_bounds__(128) void ln_kernel(
    const float* __restrict__ in, const float* __restrict__ gg,
    const float* __restrict__ bb, float* __restrict__ out,
    __half* __restrict__ outh)
{
    const int row = blockIdx.x, tid = threadIdx.x;
    const float* p = in + (size_t)row * DMODEL;
    float4 v = *(const float4*)(p + tid * 4);
    float s  = v.x + v.y + v.z + v.w;
    float ss = v.x * v.x + v.y * v.y + v.z * v.z + v.w * v.w;
#pragma unroll
    for (int o = 16; o > 0; o >>= 1) {
        s  += __shfl_xor_sync(0xffffffffu, s,  o);
        ss += __shfl_xor_sync(0xffffffffu, ss, o);
    }
    __shared__ float sh[8];
    const int w = tid >> 5, ln = tid & 31;
    if (ln == 0) { sh[w] = s; sh[4 + w] = ss; }
    __syncthreads();
    s  = sh[0] + sh[1] + sh[2] + sh[3];
    ss = sh[4] + sh[5] + sh[6] + sh[7];
    const float mu  = s * (1.0f / DMODEL);
    const float var = ss * (1.0f / DMODEL) - mu * mu;
    const float inv = rsqrtf(var + 1e-5f);
    float4 gv = *(const float4*)(gg + tid * 4);
    float4 bv = *(const float4*)(bb + tid * 4);
    float4 o4;
    o4.x = (v.x - mu) * inv * gv.x + bv.x;
    o4.y = (v.y - mu) * inv * gv.y + bv.y;
    o4.z = (v.z - mu) * inv * gv.z + bv.z;
    o4.w = (v.w - mu) * inv * gv.w + bv.w;
    *(float4*)(out + (size_t)row * DMODEL + tid * 4) = o4;
    if (EMITH) {
        *(__half2*)(outh + (size_t)row * DMODEL + tid * 4)     = __floats2half2_rn(o4.x, o4.y);
        *(__half2*)(outh + (size_t)row * DMODEL + tid * 4 + 2) = __floats2half2_rn(o4.z, o4.w);
    }
}

// ---------------------------------------------------------------------------
extern "C" void kernel_launch(void* const* d_in, const int* in_sizes, int n_in,
                              void* d_out, int out_size)
{
    const float* x      = (const float*)d_in[0];
    const int*   mask   = (const int*)  d_in[1];
    const float* qkv_w  = (const float*)d_in[2];
    const float* qkv_b  = (const float*)d_in[3];
    const float* out_w  = (const float*)d_in[4];
    const float* out_b  = (const float*)d_in[5];
    const float* ffn_w1 = (const float*)d_in[6];
    const float* ffn_b1 = (const float*)d_in[7];
    const float* ffn_w2 = (const float*)d_in[8];
    const float* ffn_b2 = (const float*)d_in[9];
    const float* ln1_g  = (const float*)d_in[10];
    const float* ln1_b  = (const float*)d_in[11];
    const float* ln2_g  = (const float*)d_in[12];
    const float* ln2_b  = (const float*)d_in[13];
    float* out = (float*)d_out;

    __half *qkvh, *attnh, *ffnh, *xh, *x1h, *qkvwT, *outwT, *ffn1T, *ffn2T;
    float *x1p, *prep;
    cudaGetSymbolAddress((void**)&qkvh,  g_qkvh);
    cudaGetSymbolAddress((void**)&attnh, g_attnh);
    cudaGetSymbolAddress((void**)&ffnh,  g_ffnh);
    cudaGetSymbolAddress((void**)&xh,    g_xh);
    cudaGetSymbolAddress((void**)&x1h,   g_x1h);
    cudaGetSymbolAddress((void**)&x1p,   g_x1);
    cudaGetSymbolAddress((void**)&prep,  g_pre);
    cudaGetSymbolAddress((void**)&qkvwT, g_qkvwT);
    cudaGetSymbolAddress((void**)&outwT, g_outwT);
    cudaGetSymbolAddress((void**)&ffn1T, g_ffn1T);
    cudaGetSymbolAddress((void**)&ffn2T, g_ffn2T);

    cudaFuncSetAttribute(hgemm_kernel<0,0,1>, cudaFuncAttributeMaxDynamicSharedMemorySize, GSMEM);
    cudaFuncSetAttribute(hgemm_kernel<0,1,0>, cudaFuncAttributeMaxDynamicSharedMemorySize, GSMEM);
    cudaFuncSetAttribute(hgemm_kernel<1,0,1>, cudaFuncAttributeMaxDynamicSharedMemorySize, GSMEM);

    // 0) One merged prep launch: x->half + 4 weight transposes
    prep_kernel<<<7168, 256>>>(x, qkv_w, out_w, ffn_w1, ffn_w2,
                               xh, qkvwT, outwT, ffn1T, ffn2T);

    // 1) QKV = X @ qkv_w + qkv_b  -> half
    hgemm_kernel<0,0,1><<<dim3(QKV3 / 128, BL / 128), 256, GSMEM>>>(
        xh, qkvwT, qkv_b, nullptr, qkvh, nullptr, BL, QKV3, DMODEL);

    // 2) Attention -> half merged [B,L,D]
    attn_h_kernel<<<512, 128>>>(qkvh, mask, attnh);

    // 3) pre1 = x + (attn @ out_w + out_b) -> f32
    hgemm_kernel<0,1,0><<<dim3(DMODEL / 128, BL / 128), 256, GSMEM>>>(
        attnh, outwT, out_b, x, nullptr, prep, BL, DMODEL, DMODEL);

    // 4) x1 = LN1(pre1) -> f32 + half
    ln_kernel<1><<<BL, 128>>>(prep, ln1_g, ln1_b, x1p, x1h);

    // 5) h = gelu(x1 @ ffn_w1 + ffn_b1) -> half
    hgemm_kernel<1,0,1><<<dim3(FFND / 128, BL / 128), 256, GSMEM>>>(
        x1h, ffn1T, ffn_b1, nullptr, ffnh, nullptr, BL, FFND, DMODEL);

    // 6) pre2 = x1 + (h @ ffn_w2 + ffn_b2) -> f32
    hgemm_kernel<0,1,0><<<dim3(DMODEL / 128, BL / 128), 256, GSMEM>>>(
        ffnh, ffn2T, ffn_b2, x1p, nullptr, prep, BL, DMODEL, FFND);

    // 7) out = LN2(pre2)
    ln_kernel<0><<<BL, 128>>>(prep, ln2_g, ln2_b, out, nullptr);
}

// round 10
// speedup vs baseline: 7.7958x; 1.0663x over previous
#include <cuda_runtime.h>
#include <cuda_fp16.h>
#include <math.h>
#include <stdint.h>
#include <string.h>

#define BQ      4
#define LSEQ    2048
#define DMODEL  512
#define NHEAD   8
#define HDIM    64
#define FFND    2048
#define BL      (BQ * LSEQ)
#define QKV3    (3 * DMODEL)
#define SCHUNK  512

// Scratch (static device globals)
__device__ __half g_qkvh [BL * QKV3];
__device__ __half g_attnh[BL * DMODEL];
__device__ __half g_ffnh [BL * FFND];
__device__ __half g_xh   [BL * DMODEL];
__device__ __half g_x1h  [BL * DMODEL];
__device__ float  g_x1   [BL * DMODEL];
__device__ float  g_pre  [BL * DMODEL];
__device__ __half g_qkvwT[QKV3 * DMODEL];
__device__ __half g_outwT[DMODEL * DMODEL];
__device__ __half g_ffn1T[FFND * DMODEL];
__device__ __half g_ffn2T[DMODEL * FFND];

// ---------------------------------------------------------------------------
__device__ __forceinline__ uint32_t h2u(__half2 h) {
    uint32_t u; memcpy(&u, &h, 4); return u;
}
__device__ __forceinline__ void mma_f16(float* d, const uint32_t* a, const uint32_t* b) {
    asm volatile(
        "mma.sync.aligned.m16n8k16.row.col.f32.f16.f16.f32 "
        "{%0,%1,%2,%3}, {%4,%5,%6,%7}, {%8,%9}, {%0,%1,%2,%3};"
        : "+f"(d[0]), "+f"(d[1]), "+f"(d[2]), "+f"(d[3])
        : "r"(a[0]), "r"(a[1]), "r"(a[2]), "r"(a[3]), "r"(b[0]), "r"(b[1]));
}
__device__ __forceinline__ uint32_t smaddr(const void* p) {
    uint32_t a;
    asm("{.reg .u64 t; cvta.to.shared.u64 t, %1; cvt.u32.u64 %0, t;}" : "=r"(a) : "l"(p));
    return a;
}
#define CP16(dst, src) asm volatile("cp.async.cg.shared.global [%0], [%1], 16;" :: "r"(dst), "l"(src))
#define CPCOMMIT()     asm volatile("cp.async.commit_group;")
#define CPWAIT(n)      asm volatile("cp.async.wait_group %0;" :: "n"(n))
#define LDSM_X4(r0,r1,r2,r3,a) \
    asm volatile("ldmatrix.sync.aligned.m8n8.x4.shared.b16 {%0,%1,%2,%3}, [%4];" \
        : "=r"(r0), "=r"(r1), "=r"(r2), "=r"(r3) : "r"(a))
#define LDSM_X4T(r0,r1,r2,r3,a) \
    asm volatile("ldmatrix.sync.aligned.m8n8.x4.trans.shared.b16 {%0,%1,%2,%3}, [%4];" \
        : "=r"(r0), "=r"(r1), "=r"(r2), "=r"(r3) : "r"(a))

// ---------------------------------------------------------------------------
// FP16 tensor GEMM, smem-bandwidth-optimized: 128x128 block, 4 warps (2x2),
// warp tile 64x64 (halves fragment bytes/MAC vs 8-warp 64x32 -> 50% tensor
// ceiling). BK=32, 3-stage cp.async, ldmatrix frags, 128 thr, 2 CTAs/SM.
// ---------------------------------------------------------------------------
#define LDA_ 40
#define A_STAGE (128 * LDA_ * 2)       // 10240 bytes per stage per operand
#define NSTAGE  3
#define GSMEM   (2 * NSTAGE * A_STAGE) // 61440

template<int GELU, int HASRES, int OUTH>
__global__ __launch_bounds__(128, 2) void hgemm_kernel(
    const __half* __restrict__ A, const __half* __restrict__ BT,
    const float* __restrict__ bias, const float* __restrict__ res,
    __half* __restrict__ Ch, float* __restrict__ Cf, int M, int N, int K)
{
    extern __shared__ __half smem_dyn[];

    const int tid   = threadIdx.x;
    const int lane  = tid & 31, wid = tid >> 5;         // wid 0..3
    const int grp   = lane >> 2, qd = lane & 3;
    const int g     = lane >> 3, l7 = lane & 7;
    const int mBase = blockIdx.y * 128;
    const int nBase = blockIdx.x * 128;
    const int mWarp = (wid & 1) * 64;
    const int nWarp = (wid >> 1) * 64;

    const uint32_t aBase = smaddr(smem_dyn);
    const uint32_t bBase = aBase + NSTAGE * A_STAGE;

    // cp.async staging: 4 chunks per operand per thread (full 128x32 tiles)
    const __half* Ap[4]; const __half* Bp[4];
    uint32_t sAo[4], sBo[4];
#pragma unroll
    for (int i = 0; i < 4; i++) {
        const int c = tid + i * 128;
        const int r = c >> 2, s = (c & 3) * 8;
        Ap[i]  = A  + (size_t)(mBase + r) * K + s;
        Bp[i]  = BT + (size_t)(nBase + r) * K + s;
        sAo[i] = aBase + (r * LDA_ + s) * 2;
        sBo[i] = bBase + (r * LDA_ + s) * 2;
    }

    // ldmatrix lane geometry
    const int rowA = mWarp + (g & 1) * 8 + l7;   // + mt*16
    const int kA   = (g >> 1) * 8;               // + ks
    const int rowB = nWarp + (g >> 1) * 8 + l7;  // + j*16
    const int kB   = (g & 1) * 8;                // + ks

    float acc[4][8][4];
#pragma unroll
    for (int mt = 0; mt < 4; mt++)
#pragma unroll
        for (int nt = 0; nt < 8; nt++)
#pragma unroll
            for (int f = 0; f < 4; f++) acc[mt][nt][f] = 0.f;

    const int niter = K >> 5;

    // prologue: issue stages 0..1
#pragma unroll
    for (int s = 0; s < NSTAGE - 1; s++) {
        const int k0 = s << 5;
        const uint32_t o = s * A_STAGE;
#pragma unroll
        for (int i = 0; i < 4; i++) {
            CP16(sAo[i] + o, Ap[i] + k0);
            CP16(sBo[i] + o, Bp[i] + k0);
        }
        CPCOMMIT();
    }

    int slot = 0;
    for (int it = 0; it < niter; it++) {
        CPWAIT(NSTAGE - 2);
        __syncthreads();

        // issue tile it+2 into slot (slot+2)%3 (freed last iteration)
        if (it + NSTAGE - 1 < niter) {
            const int k0 = (it + NSTAGE - 1) << 5;
            int islot = slot + NSTAGE - 1; if (islot >= NSTAGE) islot -= NSTAGE;
            const uint32_t o = islot * A_STAGE;
#pragma unroll
            for (int i = 0; i < 4; i++) {
                CP16(sAo[i] + o, Ap[i] + k0);
                CP16(sBo[i] + o, Bp[i] + k0);
            }
        }
        CPCOMMIT();   // empty group when exhausted: keeps group-count invariant

        const uint32_t aS = aBase + slot * A_STAGE;
        const uint32_t bS = bBase + slot * A_STAGE;
#pragma unroll
        for (int ks = 0; ks < 32; ks += 16) {
            uint32_t af[4][4], bf[8][2];
#pragma unroll
            for (int mt = 0; mt < 4; mt++)
                LDSM_X4(af[mt][0], af[mt][1], af[mt][2], af[mt][3],
                        aS + (((rowA + mt * 16) * LDA_) + ks + kA) * 2);
#pragma unroll
            for (int j = 0; j < 4; j++)
                LDSM_X4(bf[2 * j][0], bf[2 * j][1], bf[2 * j + 1][0], bf[2 * j + 1][1],
                        bS + (((rowB + j * 16) * LDA_) + ks + kB) * 2);
#pragma unroll
            for (int mt = 0; mt < 4; mt++)
#pragma unroll
                for (int nt = 0; nt < 8; nt++)
                    mma_f16(acc[mt][nt], af[mt], bf[nt]);
        }
        slot++; if (slot >= NSTAGE) slot = 0;
    }

    // Epilogue
#pragma unroll
    for (int mt = 0; mt < 4; mt++) {
#pragma unroll
        for (int nt = 0; nt < 8; nt++) {
            const int row = mBase + mWarp + mt * 16 + grp;
            const int col = nBase + nWarp + nt * 8 + qd * 2;
            const float b0 = bias[col], b1 = bias[col + 1];
#pragma unroll
            for (int rr = 0; rr < 2; rr++) {
                const int r = row + rr * 8;
                const size_t base = (size_t)r * N + col;
                float v0 = acc[mt][nt][rr * 2 + 0] + b0;
                float v1 = acc[mt][nt][rr * 2 + 1] + b1;
                if (GELU) {
                    v0 = 0.5f * v0 * (1.0f + erff(v0 * 0.70710678118654752f));
                    v1 = 0.5f * v1 * (1.0f + erff(v1 * 0.70710678118654752f));
                }
                if (HASRES) {
                    float2 rv = *(const float2*)(res + base);
                    v0 += rv.x; v1 += rv.y;
                }
                if (OUTH) {
                    *(__half2*)(Ch + base) = __floats2half2_rn(v0, v1);
                } else {
                    float2 o; o.x = v0; o.y = v1;
                    *(float2*)(Cf + base) = o;
                }
            }
        }
    }
}

// ---------------------------------------------------------------------------
// Merged prep: f2h of x + 4 weight transposes in one launch.
// ---------------------------------------------------------------------------
__global__ __launch_bounds__(256) void prep_kernel(
    const float* __restrict__ x,
    const float* __restrict__ qkv_w, const float* __restrict__ out_w,
    const float* __restrict__ ffn_w1, const float* __restrict__ ffn_w2,
    __half* __restrict__ xh, __half* __restrict__ qkvwT, __half* __restrict__ outwT,
    __half* __restrict__ ffn1T, __half* __restrict__ ffn2T)
{
    int bid = blockIdx.x;
    if (bid < 4096) {
        const int i = bid * 1024 + threadIdx.x * 4;
        float4 v = *(const float4*)(x + i);
        *(__half2*)(xh + i)     = __floats2half2_rn(v.x, v.y);
        *(__half2*)(xh + i + 2) = __floats2half2_rn(v.z, v.w);
        return;
    }
    bid -= 4096;
    const float* in; __half* outp; int C, t, R;
    if (bid < 768)       { in = qkv_w;  outp = qkvwT; R = DMODEL; C = QKV3;   t = bid; }
    else if (bid < 1024) { in = out_w;  outp = outwT; R = DMODEL; C = DMODEL; t = bid - 768; }
    else if (bid < 2048) { in = ffn_w1; outp = ffn1T; R = DMODEL; C = FFND;   t = bid - 1024; }
    else                 { in = ffn_w2; outp = ffn2T; R = FFND;   C = DMODEL; t = bid - 2048; }
    const int tilesC = C >> 5;
    const int cb = (t % tilesC) * 32, rb = (t / tilesC) * 32;

    __shared__ float tt[32][33];
    const int tx = threadIdx.x & 31, ty = threadIdx.x >> 5;
#pragma unroll
    for (int j = 0; j < 4; j++)
        tt[ty + j * 8][tx] = in[(size_t)(rb + ty + j * 8) * C + cb + tx];
    __syncthreads();
#pragma unroll
    for (int j = 0; j < 4; j++)
        outp[(size_t)(cb + ty + j * 8) * R + rb + tx] = __float2half(tt[tx][ty + j * 8]);
}

// ---------------------------------------------------------------------------
// FP16 flash attention (register P, ldmatrix, cp.async 2-stage).
// ---------------------------------------------------------------------------
#define LDK_ 72
#define KV_STAGE (32 * LDK_ * 2)

__device__ __forceinline__ float qmax4(float v) {
    v = fmaxf(v, __shfl_xor_sync(0xffffffffu, v, 1));
    v = fmaxf(v, __shfl_xor_sync(0xffffffffu, v, 2));
    return v;
}
__device__ __forceinline__ float qsum4(float v) {
    v += __shfl_xor_sync(0xffffffffu, v, 1);
    v += __shfl_xor_sync(0xffffffffu, v, 2);
    return v;
}

__global__ __launch_bounds__(128, 2) void attn_h_kernel(
    const __half* __restrict__ qkv, const int* __restrict__ mask,
    __half* __restrict__ out)
{
    __shared__ __half Ks[2][32 * LDK_];
    __shared__ __half Vs[2][32 * LDK_];
    __shared__ float biasS[2][32];

    const int blk = blockIdx.x;
    const int qt  = blk & 3;
    const int c   = (blk >> 2) & 3;
    const int bh  = blk >> 4;
    const int b   = bh >> 3, h = bh & 7;
    const int tid = threadIdx.x, lane = tid & 31, wid = tid >> 5;
    const int grp = lane >> 2, qd = lane & 3;
    const int g   = lane >> 3, l7 = lane & 7;
    const int lq0 = c * SCHUNK + qt * 128 + wid * 32;

    const uint32_t kBase = smaddr(Ks);
    const uint32_t vBase = smaddr(Vs);

    const int rowK = (g >> 1) * 8 + l7;
    const int kK   = (g & 1) * 8;
    const int rowV = (g & 1) * 8 + l7;
    const int colV = (g >> 1) * 8;

    const int stRow = (tid & 63) >> 1;
    const int stSeg = (tid & 1) * 32;
    const int isV   = tid >> 6;
    const uint32_t stDst = (isV ? vBase : kBase) + (stRow * LDK_ + stSeg) * 2;
    const size_t   stSrcOff = (size_t)DMODEL + (size_t)isV * DMODEL + h * HDIM + stSeg;

    uint32_t qa[2][4][4];
#pragma unroll
    for (int mt = 0; mt < 2; mt++)
#pragma unroll
        for (int ks = 0; ks < 4; ks++) {
            const __half* q0 = qkv + (size_t)(b * LSEQ + lq0 + mt * 16 + grp) * QKV3
                               + h * HDIM + ks * 16 + 2 * qd;
            qa[mt][ks][0] = *(const uint32_t*)(q0);
            qa[mt][ks][1] = *(const uint32_t*)(q0 + (size_t)8 * QKV3);
            qa[mt][ks][2] = *(const uint32_t*)(q0 + 8);
            qa[mt][ks][3] = *(const uint32_t*)(q0 + (size_t)8 * QKV3 + 8);
        }

    float O[2][8][4];
#pragma unroll
    for (int mt = 0; mt < 2; mt++)
#pragma unroll
        for (int nt = 0; nt < 8; nt++)
#pragma unroll
            for (int f = 0; f < 4; f++) O[mt][nt][f] = 0.f;
    float mrow[2][2] = {{-1e30f, -1e30f}, {-1e30f, -1e30f}};
    float lrow[2][2] = {{0.f, 0.f}, {0.f, 0.f}};

    int k0 = (c - 1) * SCHUNK; if (k0 < 0) k0 = 0;
    int k1 = (c + 2) * SCHUNK; if (k1 > LSEQ) k1 = LSEQ;
    const int niter = (k1 - k0) >> 5;

    {
        const __half* src = qkv + (size_t)(b * LSEQ + k0 + stRow) * QKV3 + stSrcOff;
        CP16(stDst,      src);
        CP16(stDst + 16, src + 8);
        CP16(stDst + 32, src + 16);
        CP16(stDst + 48, src + 24);
        if (tid < 32) biasS[0][tid] = mask[b * LSEQ + k0 + tid] ? -1e30f : 0.f;
        CPCOMMIT();
    }

    for (int it = 0; it < niter; it++) {
        const int buf = it & 1;
        if (it + 1 < niter) {
            const int ktn = k0 + (it + 1) * 32;
            const __half* src = qkv + (size_t)(b * LSEQ + ktn + stRow) * QKV3 + stSrcOff;
            const uint32_t d = stDst + (buf ^ 1) * KV_STAGE;
            CP16(d,      src);
            CP16(d + 16, src + 8);
            CP16(d + 32, src + 16);
            CP16(d + 48, src + 24);
            if (tid < 32) biasS[buf ^ 1][tid] = mask[b * LSEQ + ktn + tid] ? -1e30f : 0.f;
            CPCOMMIT();
            CPWAIT(1);
        } else {
            CPWAIT(0);
        }
        __syncthreads();

        const uint32_t kS = kBase + buf * KV_STAGE;
        const uint32_t vS = vBase + buf * KV_STAGE;

        float sc[2][4][4];
#pragma unroll
        for (int mt = 0; mt < 2; mt++)
#pragma unroll
            for (int nt = 0; nt < 4; nt++)
#pragma unroll
                for (int f = 0; f < 4; f++) sc[mt][nt][f] = 0.f;
#pragma unroll
        for (int ks = 0; ks < 4; ks++) {
            uint32_t kb[4][2];
            LDSM_X4(kb[0][0], kb[0][1], kb[1][0], kb[1][1],
                    kS + ((rowK * LDK_) + ks * 16 + kK) * 2);
            LDSM_X4(kb[2][0], kb[2][1], kb[3][0], kb[3][1],
                    kS + (((rowK + 16) * LDK_) + ks * 16 + kK) * 2);
#pragma unroll
            for (int mt = 0; mt < 2; mt++)
#pragma unroll
                for (int nt = 0; nt < 4; nt++)
                    mma_f16(sc[mt][nt], qa[mt][ks], kb[nt]);
        }

        float bs0[4], bs1[4];
#pragma unroll
        for (int nt = 0; nt < 4; nt++) {
            bs0[nt] = biasS[buf][nt * 8 + 2 * qd];
            bs1[nt] = biasS[buf][nt * 8 + 2 * qd + 1];
        }
#pragma unroll
        for (int mt = 0; mt < 2; mt++)
#pragma unroll
            for (int nt = 0; nt < 4; nt++) {
                sc[mt][nt][0] = sc[mt][nt][0] * 0.125f + bs0[nt];
                sc[mt][nt][1] = sc[mt][nt][1] * 0.125f + bs1[nt];
                sc[mt][nt][2] = sc[mt][nt][2] * 0.125f + bs0[nt];
                sc[mt][nt][3] = sc[mt][nt][3] * 0.125f + bs1[nt];
            }

        float scl[2][2];
#pragma unroll
        for (int mt = 0; mt < 2; mt++) {
            float nm0 = -1e30f, nm1 = -1e30f;
#pragma unroll
            for (int nt = 0; nt < 4; nt++) {
                nm0 = fmaxf(nm0, fmaxf(sc[mt][nt][0], sc[mt][nt][1]));
                nm1 = fmaxf(nm1, fmaxf(sc[mt][nt][2], sc[mt][nt][3]));
            }
            nm0 = qmax4(nm0); nm1 = qmax4(nm1);
            const float m0 = fmaxf(mrow[mt][0], nm0);
            const float m1 = fmaxf(mrow[mt][1], nm1);
            scl[mt][0] = __expf(mrow[mt][0] - m0);
            scl[mt][1] = __expf(mrow[mt][1] - m1);
            lrow[mt][0] *= scl[mt][0];
            lrow[mt][1] *= scl[mt][1];
            mrow[mt][0] = m0; mrow[mt][1] = m1;
        }
#pragma unroll
        for (int mt = 0; mt < 2; mt++)
#pragma unroll
            for (int nt = 0; nt < 8; nt++) {
                O[mt][nt][0] *= scl[mt][0];
                O[mt][nt][1] *= scl[mt][0];
                O[mt][nt][2] *= scl[mt][1];
                O[mt][nt][3] *= scl[mt][1];
            }

        uint32_t pf[2][2][4];
        float rs[2][2] = {{0.f, 0.f}, {0.f, 0.f}};
#pragma unroll
        for (int mt = 0; mt < 2; mt++)
#pragma unroll
            for (int nt = 0; nt < 4; nt++) {
                const float p0 = __expf(sc[mt][nt][0] - mrow[mt][0]);
                const float p1 = __expf(sc[mt][nt][1] - mrow[mt][0]);
                const float p2 = __expf(sc[mt][nt][2] - mrow[mt][1]);
                const float p3 = __expf(sc[mt][nt][3] - mrow[mt][1]);
                rs[mt][0] += p0 + p1;
                rs[mt][1] += p2 + p3;
                const int ks = nt >> 1, hf = nt & 1;
                pf[mt][ks][hf * 2 + 0] = h2u(__floats2half2_rn(p0, p1));
                pf[mt][ks][hf * 2 + 1] = h2u(__floats2half2_rn(p2, p3));
            }
#pragma unroll
        for (int mt = 0; mt < 2; mt++) {
            lrow[mt][0] += qsum4(rs[mt][0]);
            lrow[mt][1] += qsum4(rs[mt][1]);
        }

#pragma unroll
        for (int ks = 0; ks < 2; ks++) {
            uint32_t vb[8][2];
#pragma unroll
            for (int ntp = 0; ntp < 8; ntp += 2)
                LDSM_X4T(vb[ntp][0], vb[ntp][1], vb[ntp + 1][0], vb[ntp + 1][1],
                         vS + (((ks * 16 + rowV) * LDK_) + ntp * 8 + colV) * 2);
#pragma unroll
            for (int mt = 0; mt < 2; mt++)
#pragma unroll
                for (int nt = 0; nt < 8; nt++)
                    mma_f16(O[mt][nt], pf[mt][ks], vb[nt]);
        }
        __syncthreads();
    }

#pragma unroll
    for (int mt = 0; mt < 2; mt++) {
        const float inv0 = 1.0f / lrow[mt][0];
        const float inv1 = 1.0f / lrow[mt][1];
#pragma unroll
        for (int nt = 0; nt < 8; nt++) {
            const int row = lq0 + mt * 16 + grp;
            const int col = h * HDIM + nt * 8 + 2 * qd;
            *(__half2*)(out + (size_t)(b * LSEQ + row) * DMODEL + col) =
                __floats2half2_rn(O[mt][nt][0] * inv0, O[mt][nt][1] * inv0);
            *(__half2*)(out + (size_t)(b * LSEQ + row + 8) * DMODEL + col) =
                __floats2half2_rn(O[mt][nt][2] * inv1, O[mt][nt][3] * inv1);
        }
    }
}

// ---------------------------------------------------------------------------
template<int EMITH>
__global__ __launch_bounds__(128) void ln_kernel(
    const float* __restrict__ in, const float* __restrict__ gg,
    const float* __restrict__ bb, float* __restrict__ out,
    __half* __restrict__ outh)
{
    const int row = blockIdx.x, tid = threadIdx.x;
    const float* p = in + (size_t)row * DMODEL;
    float4 v = *(const float4*)(p + tid * 4);
    float s  = v.x + v.y + v.z + v.w;
    float ss = v.x * v.x + v.y * v.y + v.z * v.z + v.w * v.w;
#pragma unroll
    for (int o = 16; o > 0; o >>= 1) {
        s  += __shfl_xor_sync(0xffffffffu, s,  o);
        ss += __shfl_xor_sync(0xffffffffu, ss, o);
    }
    __shared__ float sh[8];
    const int w = tid >> 5, ln = tid & 31;
    if (ln == 0) { sh[w] = s; sh[4 + w] = ss; }
    __syncthreads();
    s  = sh[0] + sh[1] + sh[2] + sh[3];
    ss = sh[4] + sh[5] + sh[6] + sh[7];
    const float mu  = s * (1.0f / DMODEL);
    const float var = ss * (1.0f / DMODEL) - mu * mu;
    const float inv = rsqrtf(var + 1e-5f);
    float4 gv = *(const float4*)(gg + tid * 4);
    float4 bv = *(const float4*)(bb + tid * 4);
    float4 o4;
    o4.x = (v.x - mu) * inv * gv.x + bv.x;
    o4.y = (v.y - mu) * inv * gv.y + bv.y;
    o4.z = (v.z - mu) * inv * gv.z + bv.z;
    o4.w = (v.w - mu) * inv * gv.w + bv.w;
    *(float4*)(out + (size_t)row * DMODEL + tid * 4) = o4;
    if (EMITH) {
        *(__half2*)(outh + (size_t)row * DMODEL + tid * 4)     = __floats2half2_rn(o4.x, o4.y);
        *(__half2*)(outh + (size_t)row * DMODEL + tid * 4 + 2) = __floats2half2_rn(o4.z, o4.w);
    }
}

// ---------------------------------------------------------------------------
extern "C" void kernel_launch(void* const* d_in, const int* in_sizes, int n_in,
                              void* d_out, int out_size)
{
    const float* x      = (const float*)d_in[0];
    const int*   mask   = (const int*)  d_in[1];
    const float* qkv_w  = (const float*)d_in[2];
    const float* qkv_b  = (const float*)d_in[3];
    const float* out_w  = (const float*)d_in[4];
    const float* out_b  = (const float*)d_in[5];
    const float* ffn_w1 = (const float*)d_in[6];
    const float* ffn_b1 = (const float*)d_in[7];
    const float* ffn_w2 = (const float*)d_in[8];
    const float* ffn_b2 = (const float*)d_in[9];
    const float* ln1_g  = (const float*)d_in[10];
    const float* ln1_b  = (const float*)d_in[11];
    const float* ln2_g  = (const float*)d_in[12];
    const float* ln2_b  = (const float*)d_in[13];
    float* out = (float*)d_out;

    __half *qkvh, *attnh, *ffnh, *xh, *x1h, *qkvwT, *outwT, *ffn1T, *ffn2T;
    float *x1p, *prep;
    cudaGetSymbolAddress((void**)&qkvh,  g_qkvh);
    cudaGetSymbolAddress((void**)&attnh, g_attnh);
    cudaGetSymbolAddress((void**)&ffnh,  g_ffnh);
    cudaGetSymbolAddress((void**)&xh,    g_xh);
    cudaGetSymbolAddress((void**)&x1h,   g_x1h);
    cudaGetSymbolAddress((void**)&x1p,   g_x1);
    cudaGetSymbolAddress((void**)&prep,  g_pre);
    cudaGetSymbolAddress((void**)&qkvwT, g_qkvwT);
    cudaGetSymbolAddress((void**)&outwT, g_outwT);
    cudaGetSymbolAddress((void**)&ffn1T, g_ffn1T);
    cudaGetSymbolAddress((void**)&ffn2T, g_ffn2T);

    cudaFuncSetAttribute(hgemm_kernel<0,0,1>, cudaFuncAttributeMaxDynamicSharedMemorySize, GSMEM);
    cudaFuncSetAttribute(hgemm_kernel<0,1,0>, cudaFuncAttributeMaxDynamicSharedMemorySize, GSMEM);
    cudaFuncSetAttribute(hgemm_kernel<1,0,1>, cudaFuncAttributeMaxDynamicSharedMemorySize, GSMEM);

    // 0) One merged prep launch: x->half + 4 weight transposes
    prep_kernel<<<7168, 256>>>(x, qkv_w, out_w, ffn_w1, ffn_w2,
                               xh, qkvwT, outwT, ffn1T, ffn2T);

    // 1) QKV = X @ qkv_w + qkv_b  -> half
    hgemm_kernel<0,0,1><<<dim3(QKV3 / 128, BL / 128), 128, GSMEM>>>(
        xh, qkvwT, qkv_b, nullptr, qkvh, nullptr, BL, QKV3, DMODEL);

    // 2) Attention -> half merged [B,L,D]
    attn_h_kernel<<<512, 128>>>(qkvh, mask, attnh);

    // 3) pre1 = x + (attn @ out_w + out_b) -> f32
    hgemm_kernel<0,1,0><<<dim3(DMODEL / 128, BL / 128), 128, GSMEM>>>(
        attnh, outwT, out_b, x, nullptr, prep, BL, DMODEL, DMODEL);

    // 4) x1 = LN1(pre1) -> f32 + half
    ln_kernel<1><<<BL, 128>>>(prep, ln1_g, ln1_b, x1p, x1h);

    // 5) h = gelu(x1 @ ffn_w1 + ffn_b1) -> half
    hgemm_kernel<1,0,1><<<dim3(FFND / 128, BL / 128), 128, GSMEM>>>(
        x1h, ffn1T, ffn_b1, nullptr, ffnh, nullptr, BL, FFND, DMODEL);

    // 6) pre2 = x1 + (h @ ffn_w2 + ffn_b2) -> f32
    hgemm_kernel<0,1,0><<<dim3(DMODEL / 128, BL / 128), 128, GSMEM>>>(
        ffnh, ffn2T, ffn_b2, x1p, nullptr, prep, BL, DMODEL, FFND);

    // 7) out = LN2(pre2)
    ln_kernel<0><<<BL, 128>>>(prep, ln2_g, ln2_b, out, nullptr);
}